// round 4
// baseline (speedup 1.0000x reference)
#include <cuda_runtime.h>
#include <math.h>

#define NB    8
#define NPTS  2048
#define NS    1024
#define NG    30

// ---------------- persistent device scratch (no allocations) ----------------
__device__ float g_w[NB][NPTS];
__device__ float g_logw[NB][NPTS];
__device__ float g_ssx[NB][NS], g_ssy[NB][NS], g_ssz[NB][NS];
__device__ float g_scx[NB][NS], g_scy[NB][NS], g_scz[NB][NS];
__device__ float g_sw[NB][NS];
__device__ int   g_nn[NB][NS][NG];
__device__ float g_Rt[NB][NS][12];
__device__ int   g_cnt[NB][NS];
__device__ float g_dist;

// ---------------- threefry-2x32 (JAX), host+device ----------------
__host__ __device__ __forceinline__ void tf2x32(unsigned k0, unsigned k1,
                                                unsigned x0, unsigned x1,
                                                unsigned& o0, unsigned& o1) {
    unsigned ks2 = k0 ^ k1 ^ 0x1BD11BDAu;
    x0 += k0; x1 += k1;
#define TF_RND(r) { x0 += x1; x1 = (x1 << (r)) | (x1 >> (32 - (r))); x1 ^= x0; }
    TF_RND(13) TF_RND(15) TF_RND(26) TF_RND(6)
    x0 += k1;  x1 += ks2 + 1u;
    TF_RND(17) TF_RND(29) TF_RND(16) TF_RND(24)
    x0 += ks2; x1 += k0 + 2u;
    TF_RND(13) TF_RND(15) TF_RND(26) TF_RND(6)
    x0 += k0;  x1 += k1 + 3u;
    TF_RND(17) TF_RND(29) TF_RND(16) TF_RND(24)
    x0 += k1;  x1 += ks2 + 4u;
    TF_RND(13) TF_RND(15) TF_RND(26) TF_RND(6)
    x0 += ks2; x1 += k0 + 5u;
#undef TF_RND
    o0 = x0; o1 = x1;
}

__device__ __forceinline__ unsigned rbits32(unsigned ka, unsigned kb, unsigned m) {
    unsigned o0, o1;
    tf2x32(ka, kb, 0u, m, o0, o1);
    return o0 ^ o1;
}

__device__ __forceinline__ float gumbel_from_bits(unsigned bits) {
    float f = __uint_as_float((bits >> 9) | 0x3f800000u) - 1.0f;
    float u = fmaxf(1e-9f, f + 1e-9f);
    return -logf(-logf(u));
}

__device__ __forceinline__ unsigned float_mono(float x) {
    unsigned u = __float_as_uint(x);
    return (u & 0x80000000u) ? ~u : (u | 0x80000000u);
}

// ---------------- softmax + log, and g_dist reset ----------------
__global__ void softmax_kernel(const float* __restrict__ win) {
    int b = blockIdx.x, tid = threadIdx.x;
    if (b == 0 && tid == 0) g_dist = 1e8f;
    __shared__ float red[256];
    float mx = -3.402823466e38f;
    for (int n = tid; n < NPTS; n += 256) {
        float x = win[b * NPTS + n];
        if (isnan(x)) x = 1e-7f;
        if (isinf(x)) x = 1.0f;
        mx = fmaxf(mx, x);
    }
    red[tid] = mx; __syncthreads();
    for (int o = 128; o > 0; o >>= 1) { if (tid < o) red[tid] = fmaxf(red[tid], red[tid + o]); __syncthreads(); }
    mx = red[0]; __syncthreads();
    float s = 0.f;
    for (int n = tid; n < NPTS; n += 256) {
        float x = win[b * NPTS + n];
        if (isnan(x)) x = 1e-7f;
        if (isinf(x)) x = 1.0f;
        float e = expf(x - mx);
        g_w[b][n] = e;
        s += e;
    }
    red[tid] = s; __syncthreads();
    for (int o = 128; o > 0; o >>= 1) { if (tid < o) red[tid] += red[tid + o]; __syncthreads(); }
    s = red[0];
    for (int n = tid; n < NPTS; n += 256) {
        float wv = g_w[b][n] / s;
        g_w[b][n] = wv;
        g_logw[b][n] = logf(wv);
    }
}

// ---------------- seed selection: full bitonic sort of gumbel keys ----------------
__global__ void seed_kernel(const float* __restrict__ src, const float* __restrict__ tgt,
                            unsigned ka, unsigned kb) {
    int b = blockIdx.x, tid = threadIdx.x; // 512 threads
    __shared__ unsigned long long arr[NPTS];
    for (int n = tid; n < NPTS; n += 512) {
        unsigned m = (unsigned)(b * NPTS + n);
        float key = g_logw[b][n] + gumbel_from_bits(rbits32(ka, kb, m));
        unsigned uk = float_mono(key);
        arr[n] = ((unsigned long long)(~uk) << 32) | (unsigned)n;
    }
    __syncthreads();
    for (int k = 2; k <= NPTS; k <<= 1) {
        for (int j = k >> 1; j > 0; j >>= 1) {
            for (int i = tid; i < NPTS; i += 512) {
                int ixj = i ^ j;
                if (ixj > i) {
                    unsigned long long a = arr[i], c = arr[ixj];
                    bool up = ((i & k) == 0);
                    if ((a > c) == up) { arr[i] = c; arr[ixj] = a; }
                }
            }
            __syncthreads();
        }
    }
    for (int s0 = tid; s0 < NS; s0 += 512) {
        int j = (int)(arr[s0] & 0xFFFFFFFFull);
        g_ssx[b][s0] = src[(b * 3 + 0) * NPTS + j];
        g_ssy[b][s0] = src[(b * 3 + 1) * NPTS + j];
        g_ssz[b][s0] = src[(b * 3 + 2) * NPTS + j];
        g_scx[b][s0] = tgt[(b * 3 + 0) * NPTS + j];
        g_scy[b][s0] = tgt[(b * 3 + 1) * NPTS + j];
        g_scz[b][s0] = tgt[(b * 3 + 2) * NPTS + j];
        g_sw[b][s0]  = g_w[b][j];
    }
}

// ---------------- group selection: top-30 per row, warp per row ----------------
__global__ void nn_kernel(unsigned ka, unsigned kb) {
    __shared__ unsigned skeys[8][NS];
    int w = threadIdx.x >> 5, lane = threadIdx.x & 31;
    int r = blockIdx.x * 8 + w;
    int b = r >> 10, i = r & 1023;
    float six = g_ssx[b][i], siy = g_ssy[b][i], siz = g_ssz[b][i];
    float cix = g_scx[b][i], ciy = g_scy[b][i], ciz = g_scz[b][i];
    const float LOG01 = -2.3025851f; // logf(0.1f)
    for (int t = 0; t < 32; t++) {
        int j = lane + t * 32;
        float dx = six - g_ssx[b][j], dy = siy - g_ssy[b][j], dz = siz - g_ssz[b][j];
        float d1 = sqrtf(dx * dx + dy * dy + dz * dz);
        float ex = cix - g_scx[b][j], ey = ciy - g_scy[b][j], ez = ciz - g_scz[b][j];
        float d2 = sqrtf(ex * ex + ey * ey + ez * ez);
        float dd = d1 - d2;
        float lc = fmaxf(-(dd * dd) * 100.0f, LOG01); // log(clip(exp(-dd^2/0.01),0.1))
        unsigned m = (unsigned)r * 1024u + (unsigned)j;
        float key = lc + gumbel_from_bits(rbits32(ka, kb, m));
        skeys[w][j] = float_mono(key);
    }
    __syncwarp();
    for (int sel = 0; sel < NG; sel++) {
        unsigned bv = 0u; int bj = 0;
        for (int t = 0; t < 32; t++) {
            int j = lane + t * 32;
            unsigned v = skeys[w][j];
            if (v > bv) { bv = v; bj = j; }
        }
        for (int off = 16; off; off >>= 1) {
            unsigned ov = __shfl_xor_sync(0xffffffffu, bv, off);
            int      oj = __shfl_xor_sync(0xffffffffu, bj, off);
            if (ov > bv || (ov == bv && oj < bj)) { bv = ov; bj = oj; }
        }
        if (lane == 0) g_nn[b][i][sel] = bj;
        if (lane == (bj & 31)) skeys[w][bj] = 0u;
        __syncwarp();
    }
}

// ---------------- weighted Kabsch via f32 one-sided Jacobi SVD ----------------
__global__ void kabsch_kernel() {
    int id = blockIdx.x * blockDim.x + threadIdx.x;
    if (id >= NB * NS) return;
    int b = id >> 10, s = id & 1023;
    const int* nn = &g_nn[b][s][0];
    float smx = 0, smy = 0, smz = 0, cmx = 0, cmy = 0, cmz = 0, wsum = 0;
    for (int g = 0; g < NG; g++) {
        int j = nn[g];
        smx += g_ssx[b][j]; smy += g_ssy[b][j]; smz += g_ssz[b][j];
        cmx += g_scx[b][j]; cmy += g_scy[b][j]; cmz += g_scz[b][j];
        wsum += g_sw[b][j];
    }
    const float inv30 = 1.0f / 30.0f;
    smx *= inv30; smy *= inv30; smz *= inv30;
    cmx *= inv30; cmy *= inv30; cmz *= inv30;
    float winv = 1.0f / wsum;
    float H[3][3] = {};
    for (int g = 0; g < NG; g++) {
        int j = nn[g];
        float wn = g_sw[b][j] * winv;
        float ax = g_ssx[b][j] - smx, ay = g_ssy[b][j] - smy, az = g_ssz[b][j] - smz;
        float bx = g_scx[b][j] - cmx, by = g_scy[b][j] - cmy, bz = g_scz[b][j] - cmz;
        float wax = wn * ax, way = wn * ay, waz = wn * az;
        H[0][0] += wax * bx; H[0][1] += wax * by; H[0][2] += wax * bz;
        H[1][0] += way * bx; H[1][1] += way * by; H[1][2] += way * bz;
        H[2][0] += waz * bx; H[2][1] += waz * by; H[2][2] += waz * bz;
    }
    // one-sided Jacobi: W*V = U*S (columns)
    float W[3][3], V[3][3];
    for (int r = 0; r < 3; r++) for (int c = 0; c < 3; c++) { W[r][c] = H[r][c]; V[r][c] = (r == c) ? 1.f : 0.f; }
    const int PP[3] = {0, 0, 1}, QQ[3] = {1, 2, 2};
    for (int sweep = 0; sweep < 7; sweep++) {
        for (int pi = 0; pi < 3; pi++) {
            int p = PP[pi], q = QQ[pi];
            float app = W[0][p] * W[0][p] + W[1][p] * W[1][p] + W[2][p] * W[2][p];
            float aqq = W[0][q] * W[0][q] + W[1][q] * W[1][q] + W[2][q] * W[2][q];
            float apq = W[0][p] * W[0][q] + W[1][p] * W[1][q] + W[2][p] * W[2][q];
            if (fabsf(apq) < 1e-25f) continue;
            float zeta = (aqq - app) / (2.0f * apq);
            float t = copysignf(1.0f, zeta) / (fabsf(zeta) + sqrtf(1.0f + zeta * zeta));
            float cs = 1.0f / sqrtf(1.0f + t * t);
            float sn = cs * t;
            for (int r = 0; r < 3; r++) {
                float wp = W[r][p], wq = W[r][q];
                W[r][p] = cs * wp - sn * wq;
                W[r][q] = sn * wp + cs * wq;
                float vp = V[r][p], vq = V[r][q];
                V[r][p] = cs * vp - sn * vq;
                V[r][q] = sn * vp + cs * vq;
            }
        }
    }
    float n0 = W[0][0] * W[0][0] + W[1][0] * W[1][0] + W[2][0] * W[2][0];
    float n1 = W[0][1] * W[0][1] + W[1][1] * W[1][1] + W[2][1] * W[2][1];
    float n2 = W[0][2] * W[0][2] + W[1][2] * W[1][2] + W[2][2] * W[2][2];
    int i0 = 0, i1 = 1, i2 = 2;
    if (n1 > n0) { float tn = n0; n0 = n1; n1 = tn; int ti = i0; i0 = i1; i1 = ti; }
    if (n2 > n0) { float tn = n0; n0 = n2; n2 = tn; int ti = i0; i0 = i2; i2 = ti; }
    if (n2 > n1) { float tn = n1; n1 = n2; n2 = tn; int ti = i1; i1 = i2; i2 = ti; }
    float u1x = W[0][i0], u1y = W[1][i0], u1z = W[2][i0];
    float s1i = 1.0f / sqrtf(fmaxf(n0, 1e-30f));
    u1x *= s1i; u1y *= s1i; u1z *= s1i;
    float u2x = W[0][i1], u2y = W[1][i1], u2z = W[2][i1];
    float dp = u1x * u2x + u1y * u2y + u1z * u2z;
    u2x -= dp * u1x; u2y -= dp * u1y; u2z -= dp * u1z;
    float s2i = 1.0f / sqrtf(fmaxf(u2x * u2x + u2y * u2y + u2z * u2z, 1e-30f));
    u2x *= s2i; u2y *= s2i; u2z *= s2i;
    float u3x = u1y * u2z - u1z * u2y;
    float u3y = u1z * u2x - u1x * u2z;
    float u3z = u1x * u2y - u1y * u2x;
    float v1x = V[0][i0], v1y = V[1][i0], v1z = V[2][i0];
    float v2x = V[0][i1], v2y = V[1][i1], v2z = V[2][i1];
    float v3x = v1y * v2z - v1z * v2y;
    float v3y = v1z * v2x - v1x * v2z;
    float v3z = v1x * v2y - v1y * v2x;
    float R[3][3];
    R[0][0] = v1x * u1x + v2x * u2x + v3x * u3x;
    R[0][1] = v1x * u1y + v2x * u2y + v3x * u3y;
    R[0][2] = v1x * u1z + v2x * u2z + v3x * u3z;
    R[1][0] = v1y * u1x + v2y * u2x + v3y * u3x;
    R[1][1] = v1y * u1y + v2y * u2y + v3y * u3y;
    R[1][2] = v1y * u1z + v2y * u2z + v3y * u3z;
    R[2][0] = v1z * u1x + v2z * u2x + v3z * u3x;
    R[2][1] = v1z * u1y + v2z * u2y + v3z * u3y;
    R[2][2] = v1z * u1z + v2z * u2z + v3z * u3z;
    float tx = -(R[0][0] * smx + R[0][1] * smy + R[0][2] * smz) + cmx;
    float ty = -(R[1][0] * smx + R[1][1] * smy + R[1][2] * smz) + cmy;
    float tz = -(R[2][0] * smx + R[2][1] * smy + R[2][2] * smz) + cmz;
    float* o = &g_Rt[b][s][0];
    o[0] = R[0][0]; o[1] = R[0][1]; o[2] = R[0][2];
    o[3] = R[1][0]; o[4] = R[1][1]; o[5] = R[1][2];
    o[6] = R[2][0]; o[7] = R[2][1]; o[8] = R[2][2];
    o[9] = tx; o[10] = ty; o[11] = tz;
}

// ---------------- fitness: inlier counts, 8 seeds per block ----------------
__global__ void fitness_kernel(const float* __restrict__ src, const float* __restrict__ tgt) {
    int b = blockIdx.x >> 7;
    int sbase = (blockIdx.x & 127) * 8;
    __shared__ float Rt[8][12];
    __shared__ int scnt[8];
    int tid = threadIdx.x;
    if (tid < 96) Rt[tid / 12][tid % 12] = g_Rt[b][sbase + tid / 12][tid % 12];
    if (tid < 8) scnt[tid] = 0;
    __syncthreads();
    int cnt[8] = {0, 0, 0, 0, 0, 0, 0, 0};
    for (int n = tid; n < NPTS; n += 256) {
        float x  = src[(b * 3 + 0) * NPTS + n];
        float y  = src[(b * 3 + 1) * NPTS + n];
        float z  = src[(b * 3 + 2) * NPTS + n];
        float txg = tgt[(b * 3 + 0) * NPTS + n];
        float tyg = tgt[(b * 3 + 1) * NPTS + n];
        float tzg = tgt[(b * 3 + 2) * NPTS + n];
#pragma unroll
        for (int k = 0; k < 8; k++) {
            float px = fmaf(Rt[k][0], x, fmaf(Rt[k][1], y, fmaf(Rt[k][2], z, Rt[k][9])));
            float py = fmaf(Rt[k][3], x, fmaf(Rt[k][4], y, fmaf(Rt[k][5], z, Rt[k][10])));
            float pz = fmaf(Rt[k][6], x, fmaf(Rt[k][7], y, fmaf(Rt[k][8], z, Rt[k][11])));
            float dx = px - txg, dy = py - tyg, dz = pz - tzg;
            float d2 = dx * dx + dy * dy + dz * dz;
            cnt[k] += (d2 < 0.01f) ? 1 : 0;
        }
    }
#pragma unroll
    for (int k = 0; k < 8; k++) {
        int c = cnt[k];
        for (int off = 16; off; off >>= 1) c += __shfl_xor_sync(0xffffffffu, c, off);
        if ((tid & 31) == 0) atomicAdd(&scnt[k], c);
    }
    __syncthreads();
    if (tid < 8) g_cnt[b][sbase + tid] = scnt[tid];
}

// ---------------- per-iteration selection + output write ----------------
__global__ void select_kernel(float* __restrict__ out) {
    int tid = threadIdx.x, b = tid >> 5, lane = tid & 31;
    __shared__ int bc_s[8], bs_s[8];
    __shared__ int flag;
    int bc = -1, bs = 0;
    for (int j = lane; j < NS; j += 32) {
        int c = g_cnt[b][j];
        if (c > bc) { bc = c; bs = j; }
    }
    for (int off = 16; off; off >>= 1) {
        int oc = __shfl_xor_sync(0xffffffffu, bc, off);
        int os = __shfl_xor_sync(0xffffffffu, bs, off);
        if (oc > bc || (oc == bc && os < bs)) { bc = oc; bs = os; }
    }
    if (lane == 0) { bc_s[b] = bc; bs_s[b] = bs; }
    __syncthreads();
    if (tid == 0) {
        float s = 0.f;
        for (int i = 0; i < 8; i++) s += (float)bc_s[i] * (1.0f / 2048.0f);
        float vv = s * 0.125f;
        flag = (vv < g_dist) ? 1 : 0;
        if (flag) g_dist = vv;
    }
    __syncthreads();
    if (flag) {
        if (tid < 72) {
            int bb = tid / 9, e = tid % 9;
            out[tid] = g_Rt[bb][bs_s[bb]][e];
        } else if (tid < 96) {
            int q = tid - 72, bb = q / 3, e = q % 3;
            out[tid] = g_Rt[bb][bs_s[bb]][9 + e];
        }
    }
}

// ---------------- launch ----------------
extern "C" void kernel_launch(void* const* d_in, const int* in_sizes, int n_in,
                              void* d_out, int out_size) {
    // identify weights by size (16384); src/tgt are the 49152-element tensors in order
    int wi = 2;
    if (n_in >= 3) {
        if (in_sizes[0] == NB * NPTS) wi = 0;
        else if (in_sizes[1] == NB * NPTS) wi = 1;
        else wi = 2;
    }
    int si = (wi == 0) ? 1 : 0;
    int ti = si + 1; if (ti == wi) ti++;
    const float* src = (const float*)d_in[si];
    const float* tgt = (const float*)d_in[ti];
    const float* wts = (const float*)d_in[wi];
    float* out = (float*)d_out;

    softmax_kernel<<<NB, 256>>>(wts);
    for (int it = 0; it < 10; it++) {
        unsigned f0, f1, a0, a1, b0, b1;
        tf2x32(0u, 42u, 0u, (unsigned)it, f0, f1);   // fold_in(key, it)
        tf2x32(f0, f1, 0u, 0u, a0, a1);              // split -> k1
        tf2x32(f0, f1, 0u, 1u, b0, b1);              // split -> k2
        seed_kernel<<<NB, 512>>>(src, tgt, a0, a1);
        nn_kernel<<<1024, 256>>>(b0, b1);
        kabsch_kernel<<<32, 256>>>();
        fitness_kernel<<<1024, 256>>>(src, tgt);
        select_kernel<<<1, 256>>>(out);
    }
}

// round 6
// speedup vs baseline: 1.5787x; 1.5787x over previous
#include <cuda_runtime.h>
#include <math.h>

#define NB    8
#define NPTS  2048
#define NS    1024
#define NG    30
#define NIT   10

// ---------------- persistent device scratch (no allocations) ----------------
__device__ float g_w[NB][NPTS];
__device__ float g_logw[NB][NPTS];
__device__ float g_ssx[NIT][NB][NS], g_ssy[NIT][NB][NS], g_ssz[NIT][NB][NS];
__device__ float g_scx[NIT][NB][NS], g_scy[NIT][NB][NS], g_scz[NIT][NB][NS];
__device__ float g_sw[NIT][NB][NS];
__device__ int   g_nn[NIT][NB][NS][NG];
__device__ float g_Rt[NIT][NB][NS][12];
__device__ int   g_cnt[NIT][NB][NS];

struct Keys {
    unsigned sa[NIT], sb[NIT];   // seed-sampling key per iteration
    unsigned na[NIT], nb[NIT];   // group-sampling key per iteration
};

// ---------------- threefry-2x32 (JAX), host+device ----------------
__host__ __device__ __forceinline__ void tf2x32(unsigned k0, unsigned k1,
                                                unsigned x0, unsigned x1,
                                                unsigned& o0, unsigned& o1) {
    unsigned ks2 = k0 ^ k1 ^ 0x1BD11BDAu;
    x0 += k0; x1 += k1;
#define TF_RND(r) { x0 += x1; x1 = (x1 << (r)) | (x1 >> (32 - (r))); x1 ^= x0; }
    TF_RND(13) TF_RND(15) TF_RND(26) TF_RND(6)
    x0 += k1;  x1 += ks2 + 1u;
    TF_RND(17) TF_RND(29) TF_RND(16) TF_RND(24)
    x0 += ks2; x1 += k0 + 2u;
    TF_RND(13) TF_RND(15) TF_RND(26) TF_RND(6)
    x0 += k0;  x1 += k1 + 3u;
    TF_RND(17) TF_RND(29) TF_RND(16) TF_RND(24)
    x0 += k1;  x1 += ks2 + 4u;
    TF_RND(13) TF_RND(15) TF_RND(26) TF_RND(6)
    x0 += ks2; x1 += k0 + 5u;
#undef TF_RND
    o0 = x0; o1 = x1;
}

__device__ __forceinline__ unsigned rbits32(unsigned ka, unsigned kb, unsigned m) {
    unsigned o0, o1;
    tf2x32(ka, kb, 0u, m, o0, o1);
    return o0 ^ o1;
}

__device__ __forceinline__ float gumbel_from_bits(unsigned bits) {
    float f = __uint_as_float((bits >> 9) | 0x3f800000u) - 1.0f;
    float u = fmaxf(1e-9f, f + 1e-9f);
    return -logf(-logf(u));
}

__device__ __forceinline__ unsigned float_mono(float x) {
    unsigned u = __float_as_uint(x);
    return (u & 0x80000000u) ? ~u : (u | 0x80000000u);
}

// ---------------- softmax + log ----------------
__global__ void softmax_kernel(const float* __restrict__ win) {
    int b = blockIdx.x, tid = threadIdx.x;
    __shared__ float red[256];
    float mx = -3.402823466e38f;
    for (int n = tid; n < NPTS; n += 256) {
        float x = win[b * NPTS + n];
        if (isnan(x)) x = 1e-7f;
        if (isinf(x)) x = 1.0f;
        mx = fmaxf(mx, x);
    }
    red[tid] = mx; __syncthreads();
    for (int o = 128; o > 0; o >>= 1) { if (tid < o) red[tid] = fmaxf(red[tid], red[tid + o]); __syncthreads(); }
    mx = red[0]; __syncthreads();
    float s = 0.f;
    for (int n = tid; n < NPTS; n += 256) {
        float x = win[b * NPTS + n];
        if (isnan(x)) x = 1e-7f;
        if (isinf(x)) x = 1.0f;
        float e = expf(x - mx);
        g_w[b][n] = e;
        s += e;
    }
    red[tid] = s; __syncthreads();
    for (int o = 128; o > 0; o >>= 1) { if (tid < o) red[tid] += red[tid + o]; __syncthreads(); }
    s = red[0];
    for (int n = tid; n < NPTS; n += 256) {
        float wv = g_w[b][n] / s;
        g_w[b][n] = wv;
        g_logw[b][n] = logf(wv);
    }
}

// ---------------- seed selection (all iterations): bitonic sort ----------------
__global__ void seed_kernel(const float* __restrict__ src, const float* __restrict__ tgt,
                            Keys K) {
    int it = blockIdx.x >> 3, b = blockIdx.x & 7;
    int tid = threadIdx.x; // 1024 threads
    unsigned ka = K.sa[it], kb = K.sb[it];
    __shared__ unsigned long long arr[NPTS];
    for (int n = tid; n < NPTS; n += 1024) {
        unsigned m = (unsigned)(b * NPTS + n);
        float key = g_logw[b][n] + gumbel_from_bits(rbits32(ka, kb, m));
        unsigned uk = float_mono(key);
        arr[n] = ((unsigned long long)(~uk) << 32) | (unsigned)n;
    }
    __syncthreads();
    for (int k = 2; k <= NPTS; k <<= 1) {
        for (int j = k >> 1; j > 0; j >>= 1) {
            for (int i = tid; i < NPTS; i += 1024) {
                int ixj = i ^ j;
                if (ixj > i) {
                    unsigned long long a = arr[i], c = arr[ixj];
                    bool up = ((i & k) == 0);
                    if ((a > c) == up) { arr[i] = c; arr[ixj] = a; }
                }
            }
            __syncthreads();
        }
    }
    for (int s0 = tid; s0 < NS; s0 += 1024) {
        int j = (int)(arr[s0] & 0xFFFFFFFFull);
        g_ssx[it][b][s0] = src[(b * 3 + 0) * NPTS + j];
        g_ssy[it][b][s0] = src[(b * 3 + 1) * NPTS + j];
        g_ssz[it][b][s0] = src[(b * 3 + 2) * NPTS + j];
        g_scx[it][b][s0] = tgt[(b * 3 + 0) * NPTS + j];
        g_scy[it][b][s0] = tgt[(b * 3 + 1) * NPTS + j];
        g_scz[it][b][s0] = tgt[(b * 3 + 2) * NPTS + j];
        g_sw[it][b][s0]  = g_w[b][j];
    }
}

// ---------------- group selection: top-30 per row, warp per row ----------------
// Per-lane sorted top-4 register cache over that lane's 32 keys; pop on win,
// rescan smem (consumed entries zeroed) only when a lane's cache empties.
// Behavior identical to iterative global argmax with lowest-index tie-break.
__global__ void nn_kernel(Keys K) {
    __shared__ unsigned skeys[8][NS];
    int w = threadIdx.x >> 5, lane = threadIdx.x & 31;
    int r = blockIdx.x * 8 + w;              // 0..81919
    int it = r >> 13;
    int rr = r & 8191;                       // row within iteration
    int b = rr >> 10, i = rr & 1023;
    unsigned ka = K.na[it], kb = K.nb[it];
    float six = g_ssx[it][b][i], siy = g_ssy[it][b][i], siz = g_ssz[it][b][i];
    float cix = g_scx[it][b][i], ciy = g_scy[it][b][i], ciz = g_scz[it][b][i];
    const float LOG01 = -2.3025851f;

    unsigned c0 = 0, c1 = 0, c2 = 0, c3 = 0;
    int j0 = 0, j1 = 0, j2 = 0, j3 = 0;
    for (int t = 0; t < 32; t++) {
        int j = lane + t * 32;
        float dx = six - g_ssx[it][b][j], dy = siy - g_ssy[it][b][j], dz = siz - g_ssz[it][b][j];
        float d1 = sqrtf(dx * dx + dy * dy + dz * dz);
        float ex = cix - g_scx[it][b][j], ey = ciy - g_scy[it][b][j], ez = ciz - g_scz[it][b][j];
        float d2 = sqrtf(ex * ex + ey * ey + ez * ez);
        float dd = d1 - d2;
        float lc = fmaxf(-(dd * dd) * 100.0f, LOG01);
        unsigned m = (unsigned)rr * 1024u + (unsigned)j;
        float key = lc + gumbel_from_bits(rbits32(ka, kb, m));
        unsigned uk = float_mono(key);
        skeys[w][j] = uk;
        if (uk > c3) {                       // sorted insert, stable on ties
            if (uk > c1) {
                if (uk > c0) { c3 = c2; j3 = j2; c2 = c1; j2 = j1; c1 = c0; j1 = j0; c0 = uk; j0 = j; }
                else         { c3 = c2; j3 = j2; c2 = c1; j2 = j1; c1 = uk; j1 = j; }
            } else {
                if (uk > c2) { c3 = c2; j3 = j2; c2 = uk; j2 = j; }
                else         { c3 = uk; j3 = j; }
            }
        }
    }
    int nc = 4;
    __syncwarp();
    for (int sel = 0; sel < NG; sel++) {
        unsigned bv = c0; int bj = j0;
        for (int off = 16; off; off >>= 1) {
            unsigned ov = __shfl_xor_sync(0xffffffffu, bv, off);
            int      oj = __shfl_xor_sync(0xffffffffu, bj, off);
            if (ov > bv || (ov == bv && oj < bj)) { bv = ov; bj = oj; }
        }
        if (lane == 0) g_nn[it][b][i][sel] = bj;
        if ((bj & 31) == lane) {
            skeys[w][bj] = 0u;               // consume (only owner lane writes its slots)
            c0 = c1; j0 = j1; c1 = c2; j1 = j2; c2 = c3; j2 = j3; c3 = 0u; j3 = 0;
            if (--nc == 0) {                 // rare: rebuild top-4 of remaining
                c0 = c1 = c2 = c3 = 0u; j0 = j1 = j2 = j3 = 0;
                for (int t = 0; t < 32; t++) {
                    int jj = lane + t * 32;
                    unsigned v = skeys[w][jj];
                    if (v > c3) {
                        if (v > c1) {
                            if (v > c0) { c3 = c2; j3 = j2; c2 = c1; j2 = j1; c1 = c0; j1 = j0; c0 = v; j0 = jj; }
                            else        { c3 = c2; j3 = j2; c2 = c1; j2 = j1; c1 = v; j1 = jj; }
                        } else {
                            if (v > c2) { c3 = c2; j3 = j2; c2 = v; j2 = jj; }
                            else        { c3 = v; j3 = jj; }
                        }
                    }
                }
                nc = 4;
            }
        }
        __syncwarp();
    }
}

// ---------------- weighted Kabsch via f32 one-sided Jacobi SVD ----------------
__global__ void kabsch_kernel() {
    int id = blockIdx.x * blockDim.x + threadIdx.x;
    if (id >= NIT * NB * NS) return;
    int it = id >> 13, rr = id & 8191;
    int b = rr >> 10, s = rr & 1023;
    const int* nn = &g_nn[it][b][s][0];
    float smx = 0, smy = 0, smz = 0, cmx = 0, cmy = 0, cmz = 0, wsum = 0;
    for (int g = 0; g < NG; g++) {
        int j = nn[g];
        smx += g_ssx[it][b][j]; smy += g_ssy[it][b][j]; smz += g_ssz[it][b][j];
        cmx += g_scx[it][b][j]; cmy += g_scy[it][b][j]; cmz += g_scz[it][b][j];
        wsum += g_sw[it][b][j];
    }
    const float inv30 = 1.0f / 30.0f;
    smx *= inv30; smy *= inv30; smz *= inv30;
    cmx *= inv30; cmy *= inv30; cmz *= inv30;
    float winv = 1.0f / wsum;
    float H[3][3] = {};
    for (int g = 0; g < NG; g++) {
        int j = nn[g];
        float wn = g_sw[it][b][j] * winv;
        float ax = g_ssx[it][b][j] - smx, ay = g_ssy[it][b][j] - smy, az = g_ssz[it][b][j] - smz;
        float bx = g_scx[it][b][j] - cmx, by = g_scy[it][b][j] - cmy, bz = g_scz[it][b][j] - cmz;
        float wax = wn * ax, way = wn * ay, waz = wn * az;
        H[0][0] += wax * bx; H[0][1] += wax * by; H[0][2] += wax * bz;
        H[1][0] += way * bx; H[1][1] += way * by; H[1][2] += way * bz;
        H[2][0] += waz * bx; H[2][1] += waz * by; H[2][2] += waz * bz;
    }
    float W[3][3], V[3][3];
    for (int r = 0; r < 3; r++) for (int c = 0; c < 3; c++) { W[r][c] = H[r][c]; V[r][c] = (r == c) ? 1.f : 0.f; }
    const int PP[3] = {0, 0, 1}, QQ[3] = {1, 2, 2};
    for (int sweep = 0; sweep < 7; sweep++) {
        for (int pi = 0; pi < 3; pi++) {
            int p = PP[pi], q = QQ[pi];
            float app = W[0][p] * W[0][p] + W[1][p] * W[1][p] + W[2][p] * W[2][p];
            float aqq = W[0][q] * W[0][q] + W[1][q] * W[1][q] + W[2][q] * W[2][q];
            float apq = W[0][p] * W[0][q] + W[1][p] * W[1][q] + W[2][p] * W[2][q];
            if (fabsf(apq) < 1e-25f) continue;
            float zeta = (aqq - app) / (2.0f * apq);
            float t = copysignf(1.0f, zeta) / (fabsf(zeta) + sqrtf(1.0f + zeta * zeta));
            float cs = 1.0f / sqrtf(1.0f + t * t);
            float sn = cs * t;
            for (int r = 0; r < 3; r++) {
                float wp = W[r][p], wq = W[r][q];
                W[r][p] = cs * wp - sn * wq;
                W[r][q] = sn * wp + cs * wq;
                float vp = V[r][p], vq = V[r][q];
                V[r][p] = cs * vp - sn * vq;
                V[r][q] = sn * vp + cs * vq;
            }
        }
    }
    float n0 = W[0][0] * W[0][0] + W[1][0] * W[1][0] + W[2][0] * W[2][0];
    float n1 = W[0][1] * W[0][1] + W[1][1] * W[1][1] + W[2][1] * W[2][1];
    float n2 = W[0][2] * W[0][2] + W[1][2] * W[1][2] + W[2][2] * W[2][2];
    int i0 = 0, i1 = 1, i2 = 2;
    if (n1 > n0) { float tn = n0; n0 = n1; n1 = tn; int ti = i0; i0 = i1; i1 = ti; }
    if (n2 > n0) { float tn = n0; n0 = n2; n2 = tn; int ti = i0; i0 = i2; i2 = ti; }
    if (n2 > n1) { float tn = n1; n1 = n2; n2 = tn; int ti = i1; i1 = i2; i2 = ti; }
    float u1x = W[0][i0], u1y = W[1][i0], u1z = W[2][i0];
    float s1i = 1.0f / sqrtf(fmaxf(n0, 1e-30f));
    u1x *= s1i; u1y *= s1i; u1z *= s1i;
    float u2x = W[0][i1], u2y = W[1][i1], u2z = W[2][i1];
    float dp = u1x * u2x + u1y * u2y + u1z * u2z;
    u2x -= dp * u1x; u2y -= dp * u1y; u2z -= dp * u1z;
    float s2i = 1.0f / sqrtf(fmaxf(u2x * u2x + u2y * u2y + u2z * u2z, 1e-30f));
    u2x *= s2i; u2y *= s2i; u2z *= s2i;
    float u3x = u1y * u2z - u1z * u2y;
    float u3y = u1z * u2x - u1x * u2z;
    float u3z = u1x * u2y - u1y * u2x;
    float v1x = V[0][i0], v1y = V[1][i0], v1z = V[2][i0];
    float v2x = V[0][i1], v2y = V[1][i1], v2z = V[2][i1];
    float v3x = v1y * v2z - v1z * v2y;
    float v3y = v1z * v2x - v1x * v2z;
    float v3z = v1x * v2y - v1y * v2x;
    float R[3][3];
    R[0][0] = v1x * u1x + v2x * u2x + v3x * u3x;
    R[0][1] = v1x * u1y + v2x * u2y + v3x * u3y;
    R[0][2] = v1x * u1z + v2x * u2z + v3x * u3z;
    R[1][0] = v1y * u1x + v2y * u2x + v3y * u3x;
    R[1][1] = v1y * u1y + v2y * u2y + v3y * u3y;
    R[1][2] = v1y * u1z + v2y * u2z + v3y * u3z;
    R[2][0] = v1z * u1x + v2z * u2x + v3z * u3x;
    R[2][1] = v1z * u1y + v2z * u2y + v3z * u3y;
    R[2][2] = v1z * u1z + v2z * u2z + v3z * u3z;
    float tx = -(R[0][0] * smx + R[0][1] * smy + R[0][2] * smz) + cmx;
    float ty = -(R[1][0] * smx + R[1][1] * smy + R[1][2] * smz) + cmy;
    float tz = -(R[2][0] * smx + R[2][1] * smy + R[2][2] * smz) + cmz;
    float* o = &g_Rt[it][b][s][0];
    o[0] = R[0][0]; o[1] = R[0][1]; o[2] = R[0][2];
    o[3] = R[1][0]; o[4] = R[1][1]; o[5] = R[1][2];
    o[6] = R[2][0]; o[7] = R[2][1]; o[8] = R[2][2];
    o[9] = tx; o[10] = ty; o[11] = tz;
}

// ---------------- fitness: inlier counts, 8 seeds per block ----------------
__global__ void fitness_kernel(const float* __restrict__ src, const float* __restrict__ tgt) {
    int blk = blockIdx.x;
    int it = blk >> 10;
    int q = blk & 1023;
    int b = q >> 7;
    int sbase = (q & 127) * 8;
    __shared__ float Rt[8][12];
    __shared__ int scnt[8];
    int tid = threadIdx.x;
    if (tid < 96) Rt[tid / 12][tid % 12] = g_Rt[it][b][sbase + tid / 12][tid % 12];
    if (tid < 8) scnt[tid] = 0;
    __syncthreads();
    int cnt[8] = {0, 0, 0, 0, 0, 0, 0, 0};
    for (int n = tid; n < NPTS; n += 256) {
        float x   = src[(b * 3 + 0) * NPTS + n];
        float y   = src[(b * 3 + 1) * NPTS + n];
        float z   = src[(b * 3 + 2) * NPTS + n];
        float txg = tgt[(b * 3 + 0) * NPTS + n];
        float tyg = tgt[(b * 3 + 1) * NPTS + n];
        float tzg = tgt[(b * 3 + 2) * NPTS + n];
#pragma unroll
        for (int k = 0; k < 8; k++) {
            float px = fmaf(Rt[k][0], x, fmaf(Rt[k][1], y, fmaf(Rt[k][2], z, Rt[k][9])));
            float py = fmaf(Rt[k][3], x, fmaf(Rt[k][4], y, fmaf(Rt[k][5], z, Rt[k][10])));
            float pz = fmaf(Rt[k][6], x, fmaf(Rt[k][7], y, fmaf(Rt[k][8], z, Rt[k][11])));
            float dx = px - txg, dy = py - tyg, dz = pz - tzg;
            float d2 = dx * dx + dy * dy + dz * dz;
            cnt[k] += (d2 < 0.01f) ? 1 : 0;
        }
    }
#pragma unroll
    for (int k = 0; k < 8; k++) {
        int c = cnt[k];
        for (int off = 16; off; off >>= 1) c += __shfl_xor_sync(0xffffffffu, c, off);
        if ((tid & 31) == 0) atomicAdd(&scnt[k], c);
    }
    __syncthreads();
    if (tid < 8) g_cnt[it][b][sbase + tid] = scnt[tid];
}

// ---------------- final selection across all iterations ----------------
__global__ void select_kernel(float* __restrict__ out) {
    int tid = threadIdx.x, b = tid >> 5, lane = tid & 31;
    __shared__ int bc_s[8], bs_s[8];
    __shared__ int flag;
    __shared__ float dist_s;
    if (tid == 0) dist_s = 1e8f;
    __syncthreads();
    for (int it = 0; it < NIT; it++) {
        int bc = -1, bs = 0;
        for (int j = lane; j < NS; j += 32) {
            int c = g_cnt[it][b][j];
            if (c > bc) { bc = c; bs = j; }
        }
        for (int off = 16; off; off >>= 1) {
            int oc = __shfl_xor_sync(0xffffffffu, bc, off);
            int os = __shfl_xor_sync(0xffffffffu, bs, off);
            if (oc > bc || (oc == bc && os < bs)) { bc = oc; bs = os; }
        }
        if (lane == 0) { bc_s[b] = bc; bs_s[b] = bs; }
        __syncthreads();
        if (tid == 0) {
            float s = 0.f;
            for (int i = 0; i < 8; i++) s += (float)bc_s[i] * (1.0f / 2048.0f);
            float vv = s * 0.125f;
            flag = (vv < dist_s) ? 1 : 0;
            if (flag) dist_s = vv;
        }
        __syncthreads();
        if (flag) {
            if (tid < 72) {
                int bb = tid / 9, e = tid % 9;
                out[tid] = g_Rt[it][bb][bs_s[bb]][e];
            } else if (tid < 96) {
                int qq = tid - 72, bb = qq / 3, e = qq % 3;
                out[tid] = g_Rt[it][bb][bs_s[bb]][9 + e];
            }
        }
        __syncthreads();
    }
}

// ---------------- launch ----------------
extern "C" void kernel_launch(void* const* d_in, const int* in_sizes, int n_in,
                              void* d_out, int out_size) {
    int wi = 2;
    if (n_in >= 3) {
        if (in_sizes[0] == NB * NPTS) wi = 0;
        else if (in_sizes[1] == NB * NPTS) wi = 1;
        else wi = 2;
    }
    int si = (wi == 0) ? 1 : 0;
    int ti = si + 1; if (ti == wi) ti++;
    const float* src = (const float*)d_in[si];
    const float* tgt = (const float*)d_in[ti];
    const float* wts = (const float*)d_in[wi];
    float* out = (float*)d_out;

    Keys K;
    for (int it = 0; it < NIT; it++) {
        unsigned f0, f1;
        tf2x32(0u, 42u, 0u, (unsigned)it, f0, f1);        // fold_in(key, it)
        tf2x32(f0, f1, 0u, 0u, K.sa[it], K.sb[it]);       // split -> k1
        tf2x32(f0, f1, 0u, 1u, K.na[it], K.nb[it]);       // split -> k2
    }

    softmax_kernel<<<NB, 256>>>(wts);
    seed_kernel<<<NIT * NB, 1024>>>(src, tgt, K);
    nn_kernel<<<NIT * 1024, 256>>>(K);
    kabsch_kernel<<<320, 256>>>();
    fitness_kernel<<<NIT * 1024, 256>>>(src, tgt);
    select_kernel<<<1, 256>>>(out);
}

// round 8
// speedup vs baseline: 2.0737x; 1.3135x over previous
#include <cuda_runtime.h>
#include <math.h>

#define NB    8
#define NPTS  2048
#define NS    1024
#define NG    30
#define NIT   10

// ---------------- persistent device scratch (no allocations) ----------------
__device__ float  g_w[NB][NPTS];
__device__ float  g_logw[NB][NPTS];
__device__ float4 g_src4[NB][NPTS];            // packed src xyz
__device__ float4 g_tgt4[NB][NPTS];            // packed tgt xyz
__device__ float4 g_s4[NIT][NB][NS];           // seed src xyz + weight
__device__ float4 g_c4[NIT][NB][NS];           // seed corr xyz
__device__ int    g_nn[NIT][NB][NS][NG];
__device__ float  g_Rt[NIT][NB][NS][12];
__device__ int    g_cnt[NIT][NB][NS];

struct Keys {
    unsigned sa[NIT], sb[NIT];
    unsigned na[NIT], nb[NIT];
};

// ---------------- threefry-2x32 (JAX), host+device ----------------
__host__ __device__ __forceinline__ void tf2x32(unsigned k0, unsigned k1,
                                                unsigned x0, unsigned x1,
                                                unsigned& o0, unsigned& o1) {
    unsigned ks2 = k0 ^ k1 ^ 0x1BD11BDAu;
    x0 += k0; x1 += k1;
#define TF_RND(r) { x0 += x1; x1 = (x1 << (r)) | (x1 >> (32 - (r))); x1 ^= x0; }
    TF_RND(13) TF_RND(15) TF_RND(26) TF_RND(6)
    x0 += k1;  x1 += ks2 + 1u;
    TF_RND(17) TF_RND(29) TF_RND(16) TF_RND(24)
    x0 += ks2; x1 += k0 + 2u;
    TF_RND(13) TF_RND(15) TF_RND(26) TF_RND(6)
    x0 += k0;  x1 += k1 + 3u;
    TF_RND(17) TF_RND(29) TF_RND(16) TF_RND(24)
    x0 += k1;  x1 += ks2 + 4u;
    TF_RND(13) TF_RND(15) TF_RND(26) TF_RND(6)
    x0 += ks2; x1 += k0 + 5u;
#undef TF_RND
    o0 = x0; o1 = x1;
}

__device__ __forceinline__ unsigned rbits32(unsigned ka, unsigned kb, unsigned m) {
    unsigned o0, o1;
    tf2x32(ka, kb, 0u, m, o0, o1);
    return o0 ^ o1;
}

__device__ __forceinline__ float gumbel_from_bits(unsigned bits) {
    float f = __uint_as_float((bits >> 9) | 0x3f800000u) - 1.0f;
    float u = fmaxf(1e-9f, f + 1e-9f);
    return -logf(-logf(u));
}

__device__ __forceinline__ unsigned float_mono(float x) {
    unsigned u = __float_as_uint(x);
    return (u & 0x80000000u) ? ~u : (u | 0x80000000u);
}

// ---------------- softmax + log + pack src/tgt as float4 ----------------
__global__ void softmax_kernel(const float* __restrict__ win,
                               const float* __restrict__ src,
                               const float* __restrict__ tgt) {
    int b = blockIdx.x, tid = threadIdx.x;
    __shared__ float red[256];
    float mx = -3.402823466e38f;
    for (int n = tid; n < NPTS; n += 256) {
        float x = win[b * NPTS + n];
        if (isnan(x)) x = 1e-7f;
        if (isinf(x)) x = 1.0f;
        mx = fmaxf(mx, x);
    }
    red[tid] = mx; __syncthreads();
    for (int o = 128; o > 0; o >>= 1) { if (tid < o) red[tid] = fmaxf(red[tid], red[tid + o]); __syncthreads(); }
    mx = red[0]; __syncthreads();
    float s = 0.f;
    for (int n = tid; n < NPTS; n += 256) {
        float x = win[b * NPTS + n];
        if (isnan(x)) x = 1e-7f;
        if (isinf(x)) x = 1.0f;
        float e = expf(x - mx);
        g_w[b][n] = e;
        s += e;
    }
    red[tid] = s; __syncthreads();
    for (int o = 128; o > 0; o >>= 1) { if (tid < o) red[tid] += red[tid + o]; __syncthreads(); }
    s = red[0];
    for (int n = tid; n < NPTS; n += 256) {
        float wv = g_w[b][n] / s;
        g_w[b][n] = wv;
        g_logw[b][n] = logf(wv);
        g_src4[b][n] = make_float4(src[(b * 3 + 0) * NPTS + n],
                                   src[(b * 3 + 1) * NPTS + n],
                                   src[(b * 3 + 2) * NPTS + n], 0.f);
        g_tgt4[b][n] = make_float4(tgt[(b * 3 + 0) * NPTS + n],
                                   tgt[(b * 3 + 1) * NPTS + n],
                                   tgt[(b * 3 + 2) * NPTS + n], 0.f);
    }
}

// ---------------- seed selection (all iterations): bitonic sort ----------------
__global__ void seed_kernel(Keys K) {
    int it = blockIdx.x >> 3, b = blockIdx.x & 7;
    int tid = threadIdx.x; // 1024 threads
    unsigned ka = K.sa[it], kb = K.sb[it];
    __shared__ unsigned long long arr[NPTS];
    for (int n = tid; n < NPTS; n += 1024) {
        unsigned m = (unsigned)(b * NPTS + n);
        float key = g_logw[b][n] + gumbel_from_bits(rbits32(ka, kb, m));
        unsigned uk = float_mono(key);
        arr[n] = ((unsigned long long)(~uk) << 32) | (unsigned)n;
    }
    __syncthreads();
    for (int k = 2; k <= NPTS; k <<= 1) {
        for (int j = k >> 1; j > 0; j >>= 1) {
            for (int i = tid; i < NPTS; i += 1024) {
                int ixj = i ^ j;
                if (ixj > i) {
                    unsigned long long a = arr[i], c = arr[ixj];
                    bool up = ((i & k) == 0);
                    if ((a > c) == up) { arr[i] = c; arr[ixj] = a; }
                }
            }
            __syncthreads();
        }
    }
    for (int s0 = tid; s0 < NS; s0 += 1024) {
        int j = (int)(arr[s0] & 0xFFFFFFFFull);
        float4 sp = g_src4[b][j];
        sp.w = g_w[b][j];
        g_s4[it][b][s0] = sp;
        g_c4[it][b][s0] = g_tgt4[b][j];
    }
}

// ---------------- group selection: top-30 per row, warp per row ----------------
// Per-lane top-6 register cache + consumed bitmask; recompute (bit-identical,
// pinned arithmetic) on the rare cache-empty. No shared memory.
__global__ void __launch_bounds__(256, 4) nn_kernel(Keys K) {
    int w = threadIdx.x >> 5, lane = threadIdx.x & 31;
    int r = blockIdx.x * 8 + w;
    int it = r >> 13;
    int rr = r & 8191;
    int b = rr >> 10, i = rr & 1023;
    unsigned ka = K.na[it], kb = K.nb[it];
    const float4* __restrict__ S = &g_s4[it][b][0];
    const float4* __restrict__ C = &g_c4[it][b][0];
    float4 si = S[i], ci = C[i];

    unsigned c0 = 0, c1 = 0, c2 = 0, c3 = 0, c4 = 0, c5 = 0;
    int j0 = 0, j1 = 0, j2 = 0, j3 = 0, j4 = 0, j5 = 0;

#define KEYFOR(jv, ukv) { \
    float4 sj = S[jv], cjv = C[jv]; \
    float dx = si.x - sj.x, dy = si.y - sj.y, dz = si.z - sj.z; \
    float ex = ci.x - cjv.x, ey = ci.y - cjv.y, ez = ci.z - cjv.z; \
    float d1 = sqrtf(__fmaf_rn(dx, dx, __fmaf_rn(dy, dy, __fmul_rn(dz, dz)))); \
    float d2 = sqrtf(__fmaf_rn(ex, ex, __fmaf_rn(ey, ey, __fmul_rn(ez, ez)))); \
    float dd = d1 - d2; \
    float lc = fmaxf(-__fmul_rn(__fmul_rn(dd, dd), 100.0f), -2.3025851f); \
    ukv = float_mono(lc + gumbel_from_bits(rbits32(ka, kb, (unsigned)rr * 1024u + (unsigned)(jv)))); \
}

#define INSERT6(uk, jn) { \
    if ((uk) > c5) { \
      if ((uk) > c2) { \
        if ((uk) > c1) { \
          if ((uk) > c0) { c5=c4;j5=j4;c4=c3;j4=j3;c3=c2;j3=j2;c2=c1;j2=j1;c1=c0;j1=j0;c0=(uk);j0=(jn); } \
          else           { c5=c4;j5=j4;c4=c3;j4=j3;c3=c2;j3=j2;c2=c1;j2=j1;c1=(uk);j1=(jn); } \
        } else           { c5=c4;j5=j4;c4=c3;j4=j3;c3=c2;j3=j2;c2=(uk);j2=(jn); } \
      } else { \
        if ((uk) > c4) { \
          if ((uk) > c3) { c5=c4;j5=j4;c4=c3;j4=j3;c3=(uk);j3=(jn); } \
          else           { c5=c4;j5=j4;c4=(uk);j4=(jn); } \
        } else           { c5=(uk);j5=(jn); } \
      } \
    } }

#pragma unroll 4
    for (int t = 0; t < 32; t++) {
        int j = lane + t * 32;
        unsigned uk; KEYFOR(j, uk);
        INSERT6(uk, j);
    }
    int nc = 6;
    unsigned mask = 0u;
    int* out = &g_nn[it][b][i][0];
    for (int sel = 0; sel < NG; sel++) {
        unsigned bv = c0; int bj = j0;
#pragma unroll
        for (int off = 16; off; off >>= 1) {
            unsigned ov = __shfl_xor_sync(0xffffffffu, bv, off);
            int      oj = __shfl_xor_sync(0xffffffffu, bj, off);
            if (ov > bv || (ov == bv && oj < bj)) { bv = ov; bj = oj; }
        }
        if (lane == 0) out[sel] = bj;
        if ((bj & 31) == lane) {
            mask |= 1u << (bj >> 5);
            c0 = c1; j0 = j1; c1 = c2; j1 = j2; c2 = c3; j2 = j3;
            c3 = c4; j3 = j4; c4 = c5; j4 = j5; c5 = 0u; j5 = 0;
            if (--nc == 0) {
                c0 = c1 = c2 = c3 = c4 = c5 = 0u;
                j0 = j1 = j2 = j3 = j4 = j5 = 0;
                for (int t = 0; t < 32; t++) {
                    if ((mask >> t) & 1u) continue;
                    int jj = lane + t * 32;
                    unsigned uk; KEYFOR(jj, uk);
                    INSERT6(uk, jj);
                }
                int rem = 32 - __popc(mask);
                nc = rem < 6 ? rem : 6;
                if (nc == 0) nc = 1000;
            }
        }
        __syncwarp();
    }
#undef KEYFOR
#undef INSERT6
}

// ---------------- weighted Kabsch via f32 one-sided Jacobi SVD ----------------
__global__ void kabsch_kernel() {
    int id = blockIdx.x * blockDim.x + threadIdx.x;
    if (id >= NIT * NB * NS) return;
    int it = id >> 13, rr = id & 8191;
    int b = rr >> 10, s = rr & 1023;
    const int* nn = &g_nn[it][b][s][0];
    const float4* __restrict__ S = &g_s4[it][b][0];
    const float4* __restrict__ C = &g_c4[it][b][0];
    float smx = 0, smy = 0, smz = 0, cmx = 0, cmy = 0, cmz = 0, wsum = 0;
    for (int g = 0; g < NG; g++) {
        int j = nn[g];
        float4 sp = S[j], cp = C[j];
        smx += sp.x; smy += sp.y; smz += sp.z;
        cmx += cp.x; cmy += cp.y; cmz += cp.z;
        wsum += sp.w;
    }
    const float inv30 = 1.0f / 30.0f;
    smx *= inv30; smy *= inv30; smz *= inv30;
    cmx *= inv30; cmy *= inv30; cmz *= inv30;
    float winv = 1.0f / wsum;
    float H[3][3] = {};
    for (int g = 0; g < NG; g++) {
        int j = nn[g];
        float4 sp = S[j], cp = C[j];
        float wn = sp.w * winv;
        float ax = sp.x - smx, ay = sp.y - smy, az = sp.z - smz;
        float bx = cp.x - cmx, by = cp.y - cmy, bz = cp.z - cmz;
        float wax = wn * ax, way = wn * ay, waz = wn * az;
        H[0][0] += wax * bx; H[0][1] += wax * by; H[0][2] += wax * bz;
        H[1][0] += way * bx; H[1][1] += way * by; H[1][2] += way * bz;
        H[2][0] += waz * bx; H[2][1] += waz * by; H[2][2] += waz * bz;
    }
    float W[3][3], V[3][3];
    for (int r = 0; r < 3; r++) for (int c = 0; c < 3; c++) { W[r][c] = H[r][c]; V[r][c] = (r == c) ? 1.f : 0.f; }
    const int PP[3] = {0, 0, 1}, QQ[3] = {1, 2, 2};
    for (int sweep = 0; sweep < 7; sweep++) {
        for (int pi = 0; pi < 3; pi++) {
            int p = PP[pi], q = QQ[pi];
            float app = W[0][p] * W[0][p] + W[1][p] * W[1][p] + W[2][p] * W[2][p];
            float aqq = W[0][q] * W[0][q] + W[1][q] * W[1][q] + W[2][q] * W[2][q];
            float apq = W[0][p] * W[0][q] + W[1][p] * W[1][q] + W[2][p] * W[2][q];
            if (fabsf(apq) < 1e-25f) continue;
            float zeta = (aqq - app) / (2.0f * apq);
            float t = copysignf(1.0f, zeta) / (fabsf(zeta) + sqrtf(1.0f + zeta * zeta));
            float cs = 1.0f / sqrtf(1.0f + t * t);
            float sn = cs * t;
            for (int r = 0; r < 3; r++) {
                float wp = W[r][p], wq = W[r][q];
                W[r][p] = cs * wp - sn * wq;
                W[r][q] = sn * wp + cs * wq;
                float vp = V[r][p], vq = V[r][q];
                V[r][p] = cs * vp - sn * vq;
                V[r][q] = sn * vp + cs * vq;
            }
        }
    }
    float n0 = W[0][0] * W[0][0] + W[1][0] * W[1][0] + W[2][0] * W[2][0];
    float n1 = W[0][1] * W[0][1] + W[1][1] * W[1][1] + W[2][1] * W[2][1];
    float n2 = W[0][2] * W[0][2] + W[1][2] * W[1][2] + W[2][2] * W[2][2];
    int i0 = 0, i1 = 1, i2 = 2;
    if (n1 > n0) { float tn = n0; n0 = n1; n1 = tn; int ti = i0; i0 = i1; i1 = ti; }
    if (n2 > n0) { float tn = n0; n0 = n2; n2 = tn; int ti = i0; i0 = i2; i2 = ti; }
    if (n2 > n1) { float tn = n1; n1 = n2; n2 = tn; int ti = i1; i1 = i2; i2 = ti; }
    float u1x = W[0][i0], u1y = W[1][i0], u1z = W[2][i0];
    float s1i = 1.0f / sqrtf(fmaxf(n0, 1e-30f));
    u1x *= s1i; u1y *= s1i; u1z *= s1i;
    float u2x = W[0][i1], u2y = W[1][i1], u2z = W[2][i1];
    float dp = u1x * u2x + u1y * u2y + u1z * u2z;
    u2x -= dp * u1x; u2y -= dp * u1y; u2z -= dp * u1z;
    float s2i = 1.0f / sqrtf(fmaxf(u2x * u2x + u2y * u2y + u2z * u2z, 1e-30f));
    u2x *= s2i; u2y *= s2i; u2z *= s2i;
    float u3x = u1y * u2z - u1z * u2y;
    float u3y = u1z * u2x - u1x * u2z;
    float u3z = u1x * u2y - u1y * u2x;
    float v1x = V[0][i0], v1y = V[1][i0], v1z = V[2][i0];
    float v2x = V[0][i1], v2y = V[1][i1], v2z = V[2][i1];
    float v3x = v1y * v2z - v1z * v2y;
    float v3y = v1z * v2x - v1x * v2z;
    float v3z = v1x * v2y - v1y * v2x;
    float R[3][3];
    R[0][0] = v1x * u1x + v2x * u2x + v3x * u3x;
    R[0][1] = v1x * u1y + v2x * u2y + v3x * u3y;
    R[0][2] = v1x * u1z + v2x * u2z + v3x * u3z;
    R[1][0] = v1y * u1x + v2y * u2x + v3y * u3x;
    R[1][1] = v1y * u1y + v2y * u2y + v3y * u3y;
    R[1][2] = v1y * u1z + v2y * u2z + v3y * u3z;
    R[2][0] = v1z * u1x + v2z * u2x + v3z * u3x;
    R[2][1] = v1z * u1y + v2z * u2y + v3z * u3y;
    R[2][2] = v1z * u1z + v2z * u2z + v3z * u3z;
    float tx = -(R[0][0] * smx + R[0][1] * smy + R[0][2] * smz) + cmx;
    float ty = -(R[1][0] * smx + R[1][1] * smy + R[1][2] * smz) + cmy;
    float tz = -(R[2][0] * smx + R[2][1] * smy + R[2][2] * smz) + cmz;
    float* o = &g_Rt[it][b][s][0];
    o[0] = R[0][0]; o[1] = R[0][1]; o[2] = R[0][2];
    o[3] = R[1][0]; o[4] = R[1][1]; o[5] = R[1][2];
    o[6] = R[2][0]; o[7] = R[2][1]; o[8] = R[2][2];
    o[9] = tx; o[10] = ty; o[11] = tz;
}

// ---------------- fitness: one seed per thread, staged points ----------------
__global__ void __launch_bounds__(128) fitness_kernel() {
    int blk = blockIdx.x;              // 0..639
    int it = blk >> 6;
    int q = blk & 63;
    int b = q >> 3;
    int s = ((q & 7) << 7) + threadIdx.x;
    int tid = threadIdx.x;
    const float4* rt4 = (const float4*)&g_Rt[it][b][s][0];
    float4 A = rt4[0], B4 = rt4[1], C4 = rt4[2];
    // A=(R00,R01,R02,R10) B4=(R11,R12,R20,R21) C4=(R22,tx,ty,tz)
    __shared__ float4 sp[256], tp[256];
    int cnt = 0;
    for (int cb = 0; cb < NPTS; cb += 256) {
        __syncthreads();
        for (int p = tid; p < 256; p += 128) {
            sp[p] = g_src4[b][cb + p];
            tp[p] = g_tgt4[b][cb + p];
        }
        __syncthreads();
#pragma unroll 4
        for (int p = 0; p < 256; p++) {
            float4 P = sp[p], T = tp[p];
            float px = __fmaf_rn(A.x, P.x, __fmaf_rn(A.y, P.y, __fmaf_rn(A.z, P.z, C4.y)));
            float py = __fmaf_rn(A.w, P.x, __fmaf_rn(B4.x, P.y, __fmaf_rn(B4.y, P.z, C4.z)));
            float pz = __fmaf_rn(B4.z, P.x, __fmaf_rn(B4.w, P.y, __fmaf_rn(C4.x, P.z, C4.w)));
            float dx = px - T.x, dy = py - T.y, dz = pz - T.z;
            float d2 = __fmaf_rn(dx, dx, __fmaf_rn(dy, dy, __fmul_rn(dz, dz)));
            cnt += (d2 < 0.01f) ? 1 : 0;
        }
    }
    g_cnt[it][b][s] = cnt;
}

// ---------------- final selection across all iterations ----------------
__global__ void select_kernel(float* __restrict__ out) {
    int tid = threadIdx.x, b = tid >> 5, lane = tid & 31;
    __shared__ int bc_s[8], bs_s[8];
    __shared__ int flag;
    __shared__ float dist_s;
    if (tid == 0) dist_s = 1e8f;
    __syncthreads();
    for (int it = 0; it < NIT; it++) {
        int bc = -1, bs = 0;
        for (int j = lane; j < NS; j += 32) {
            int c = g_cnt[it][b][j];
            if (c > bc) { bc = c; bs = j; }
        }
        for (int off = 16; off; off >>= 1) {
            int oc = __shfl_xor_sync(0xffffffffu, bc, off);
            int os = __shfl_xor_sync(0xffffffffu, bs, off);
            if (oc > bc || (oc == bc && os < bs)) { bc = oc; bs = os; }
        }
        if (lane == 0) { bc_s[b] = bc; bs_s[b] = bs; }
        __syncthreads();
        if (tid == 0) {
            float s = 0.f;
            for (int i = 0; i < 8; i++) s += (float)bc_s[i] * (1.0f / 2048.0f);
            float vv = s * 0.125f;
            flag = (vv < dist_s) ? 1 : 0;
            if (flag) dist_s = vv;
        }
        __syncthreads();
        if (flag) {
            if (tid < 72) {
                int bb = tid / 9, e = tid % 9;
                out[tid] = g_Rt[it][bb][bs_s[bb]][e];
            } else if (tid < 96) {
                int qq = tid - 72, bb = qq / 3, e = qq % 3;
                out[tid] = g_Rt[it][bb][bs_s[bb]][9 + e];
            }
        }
        __syncthreads();
    }
}

// ---------------- launch ----------------
extern "C" void kernel_launch(void* const* d_in, const int* in_sizes, int n_in,
                              void* d_out, int out_size) {
    int wi = 2;
    if (n_in >= 3) {
        if (in_sizes[0] == NB * NPTS) wi = 0;
        else if (in_sizes[1] == NB * NPTS) wi = 1;
        else wi = 2;
    }
    int si = (wi == 0) ? 1 : 0;
    int ti = si + 1; if (ti == wi) ti++;
    const float* src = (const float*)d_in[si];
    const float* tgt = (const float*)d_in[ti];
    const float* wts = (const float*)d_in[wi];
    float* out = (float*)d_out;

    Keys K;
    for (int it = 0; it < NIT; it++) {
        unsigned f0, f1;
        tf2x32(0u, 42u, 0u, (unsigned)it, f0, f1);
        tf2x32(f0, f1, 0u, 0u, K.sa[it], K.sb[it]);
        tf2x32(f0, f1, 0u, 1u, K.na[it], K.nb[it]);
    }

    softmax_kernel<<<NB, 256>>>(wts, src, tgt);
    seed_kernel<<<NIT * NB, 1024>>>(K);
    nn_kernel<<<NIT * 1024, 256>>>(K);
    kabsch_kernel<<<320, 256>>>();
    fitness_kernel<<<NIT * 64, 128>>>();
    select_kernel<<<1, 256>>>(out);
}

// round 10
// speedup vs baseline: 2.1496x; 1.0366x over previous
#include <cuda_runtime.h>
#include <math.h>

#define NB    8
#define NPTS  2048
#define NS    1024
#define NG    30
#define NIT   10

typedef unsigned long long ull;

// ---------------- persistent device scratch (no allocations) ----------------
__device__ float  g_w[NB][NPTS];
__device__ float  g_logw[NB][NPTS];
__device__ float4 g_src4[NB][NPTS];
__device__ float4 g_tgt4[NB][NPTS];
__device__ float4 g_s4[NIT][NB][NS];
__device__ float4 g_c4[NIT][NB][NS];
__device__ int    g_nn[NIT][NB][NS][NG];
__device__ float  g_Rt[NIT][NB][NS][12];
__device__ int    g_cnt[NIT][NB][NS];

struct Keys {
    unsigned sa[NIT], sb[NIT];
    unsigned na[NIT], nb[NIT];
};

// ---------------- threefry-2x32 (JAX), host+device ----------------
__host__ __device__ __forceinline__ void tf2x32(unsigned k0, unsigned k1,
                                                unsigned x0, unsigned x1,
                                                unsigned& o0, unsigned& o1) {
    unsigned ks2 = k0 ^ k1 ^ 0x1BD11BDAu;
    x0 += k0; x1 += k1;
#define TF_RND(r) { x0 += x1; x1 = (x1 << (r)) | (x1 >> (32 - (r))); x1 ^= x0; }
    TF_RND(13) TF_RND(15) TF_RND(26) TF_RND(6)
    x0 += k1;  x1 += ks2 + 1u;
    TF_RND(17) TF_RND(29) TF_RND(16) TF_RND(24)
    x0 += ks2; x1 += k0 + 2u;
    TF_RND(13) TF_RND(15) TF_RND(26) TF_RND(6)
    x0 += k0;  x1 += k1 + 3u;
    TF_RND(17) TF_RND(29) TF_RND(16) TF_RND(24)
    x0 += k1;  x1 += ks2 + 4u;
    TF_RND(13) TF_RND(15) TF_RND(26) TF_RND(6)
    x0 += ks2; x1 += k0 + 5u;
#undef TF_RND
    o0 = x0; o1 = x1;
}

__device__ __forceinline__ unsigned rbits32(unsigned ka, unsigned kb, unsigned m) {
    unsigned o0, o1;
    tf2x32(ka, kb, 0u, m, o0, o1);
    return o0 ^ o1;
}

__device__ __forceinline__ float gumbel_from_bits(unsigned bits) {
    float f = __uint_as_float((bits >> 9) | 0x3f800000u) - 1.0f;
    float u = fmaxf(1e-9f, f + 1e-9f);
    return -logf(-logf(u));
}

__device__ __forceinline__ unsigned float_mono(float x) {
    unsigned u = __float_as_uint(x);
    return (u & 0x80000000u) ? ~u : (u | 0x80000000u);
}

// ---------------- packed f32x2 helpers (per-element IEEE identical) ----------
#define FMA2(d,a,b,c) asm("fma.rn.f32x2 %0, %1, %2, %3;" : "=l"(d) : "l"(a), "l"(b), "l"(c))
#define ADD2(d,a,b)   asm("add.rn.f32x2 %0, %1, %2;" : "=l"(d) : "l"(a), "l"(b))
#define MUL2(d,a,b)   asm("mul.rn.f32x2 %0, %1, %2;" : "=l"(d) : "l"(a), "l"(b))

__device__ __forceinline__ ull pk2(float v) {
    ull r; asm("mov.b64 %0, {%1, %1};" : "=l"(r) : "f"(v)); return r;
}
__device__ __forceinline__ void unpk(float& lo, float& hi, ull d) {
    asm("mov.b64 {%0, %1}, %2;" : "=f"(lo), "=f"(hi) : "l"(d));
}

// ---------------- softmax + log + pack src/tgt as float4 ----------------
__global__ void softmax_kernel(const float* __restrict__ win,
                               const float* __restrict__ src,
                               const float* __restrict__ tgt) {
    int b = blockIdx.x, tid = threadIdx.x;
    __shared__ float red[256];
    float mx = -3.402823466e38f;
    for (int n = tid; n < NPTS; n += 256) {
        float x = win[b * NPTS + n];
        if (isnan(x)) x = 1e-7f;
        if (isinf(x)) x = 1.0f;
        mx = fmaxf(mx, x);
    }
    red[tid] = mx; __syncthreads();
    for (int o = 128; o > 0; o >>= 1) { if (tid < o) red[tid] = fmaxf(red[tid], red[tid + o]); __syncthreads(); }
    mx = red[0]; __syncthreads();
    float s = 0.f;
    for (int n = tid; n < NPTS; n += 256) {
        float x = win[b * NPTS + n];
        if (isnan(x)) x = 1e-7f;
        if (isinf(x)) x = 1.0f;
        float e = expf(x - mx);
        g_w[b][n] = e;
        s += e;
    }
    red[tid] = s; __syncthreads();
    for (int o = 128; o > 0; o >>= 1) { if (tid < o) red[tid] += red[tid + o]; __syncthreads(); }
    s = red[0];
    for (int n = tid; n < NPTS; n += 256) {
        float wv = g_w[b][n] / s;
        g_w[b][n] = wv;
        g_logw[b][n] = logf(wv);
        g_src4[b][n] = make_float4(src[(b * 3 + 0) * NPTS + n],
                                   src[(b * 3 + 1) * NPTS + n],
                                   src[(b * 3 + 2) * NPTS + n], 0.f);
        g_tgt4[b][n] = make_float4(tgt[(b * 3 + 0) * NPTS + n],
                                   tgt[(b * 3 + 1) * NPTS + n],
                                   tgt[(b * 3 + 2) * NPTS + n], 0.f);
    }
}

// ---------------- seed selection (all iterations): bitonic sort ----------------
__global__ void seed_kernel(Keys K) {
    int it = blockIdx.x >> 3, b = blockIdx.x & 7;
    int tid = threadIdx.x; // 1024 threads
    unsigned ka = K.sa[it], kb = K.sb[it];
    __shared__ unsigned long long arr[NPTS];
    for (int n = tid; n < NPTS; n += 1024) {
        unsigned m = (unsigned)(b * NPTS + n);
        float key = g_logw[b][n] + gumbel_from_bits(rbits32(ka, kb, m));
        unsigned uk = float_mono(key);
        arr[n] = ((unsigned long long)(~uk) << 32) | (unsigned)n;
    }
    __syncthreads();
    for (int k = 2; k <= NPTS; k <<= 1) {
        for (int j = k >> 1; j > 0; j >>= 1) {
            for (int i = tid; i < NPTS; i += 1024) {
                int ixj = i ^ j;
                if (ixj > i) {
                    unsigned long long a = arr[i], c = arr[ixj];
                    bool up = ((i & k) == 0);
                    if ((a > c) == up) { arr[i] = c; arr[ixj] = a; }
                }
            }
            __syncthreads();
        }
    }
    for (int s0 = tid; s0 < NS; s0 += 1024) {
        int j = (int)(arr[s0] & 0xFFFFFFFFull);
        float4 sp = g_src4[b][j];
        sp.w = g_w[b][j];
        g_s4[it][b][s0] = sp;
        g_c4[it][b][s0] = g_tgt4[b][j];
    }
}

// ---------------- group selection: top-30 per row, warp per row ----------------
// Per-lane top-6 register cache + consumed bitmask; recompute (bit-identical,
// pinned arithmetic) on the rare cache-empty. No launch-bounds reg clamp.
__global__ void __launch_bounds__(256) nn_kernel(Keys K) {
    int w = threadIdx.x >> 5, lane = threadIdx.x & 31;
    int r = blockIdx.x * 8 + w;
    int it = r >> 13;
    int rr = r & 8191;
    int b = rr >> 10, i = rr & 1023;
    unsigned ka = K.na[it], kb = K.nb[it];
    const float4* __restrict__ S = &g_s4[it][b][0];
    const float4* __restrict__ C = &g_c4[it][b][0];
    float4 si = S[i], ci = C[i];

    unsigned c0 = 0, c1 = 0, c2 = 0, c3 = 0, c4 = 0, c5 = 0;
    int j0 = 0, j1 = 0, j2 = 0, j3 = 0, j4 = 0, j5 = 0;

#define KEYFOR(jv, ukv) { \
    float4 sj = S[jv], cjv = C[jv]; \
    float dx = si.x - sj.x, dy = si.y - sj.y, dz = si.z - sj.z; \
    float ex = ci.x - cjv.x, ey = ci.y - cjv.y, ez = ci.z - cjv.z; \
    float d1 = sqrtf(__fmaf_rn(dx, dx, __fmaf_rn(dy, dy, __fmul_rn(dz, dz)))); \
    float d2 = sqrtf(__fmaf_rn(ex, ex, __fmaf_rn(ey, ey, __fmul_rn(ez, ez)))); \
    float dd = d1 - d2; \
    float lc = fmaxf(-__fmul_rn(__fmul_rn(dd, dd), 100.0f), -2.3025851f); \
    ukv = float_mono(lc + gumbel_from_bits(rbits32(ka, kb, (unsigned)rr * 1024u + (unsigned)(jv)))); \
}

#define INSERT6(uk, jn) { \
    if ((uk) > c5) { \
      if ((uk) > c2) { \
        if ((uk) > c1) { \
          if ((uk) > c0) { c5=c4;j5=j4;c4=c3;j4=j3;c3=c2;j3=j2;c2=c1;j2=j1;c1=c0;j1=j0;c0=(uk);j0=(jn); } \
          else           { c5=c4;j5=j4;c4=c3;j4=j3;c3=c2;j3=j2;c2=c1;j2=j1;c1=(uk);j1=(jn); } \
        } else           { c5=c4;j5=j4;c4=c3;j4=j3;c3=c2;j3=j2;c2=(uk);j2=(jn); } \
      } else { \
        if ((uk) > c4) { \
          if ((uk) > c3) { c5=c4;j5=j4;c4=c3;j4=j3;c3=(uk);j3=(jn); } \
          else           { c5=c4;j5=j4;c4=(uk);j4=(jn); } \
        } else           { c5=(uk);j5=(jn); } \
      } \
    } }

#pragma unroll 4
    for (int t = 0; t < 32; t++) {
        int j = lane + t * 32;
        unsigned uk; KEYFOR(j, uk);
        INSERT6(uk, j);
    }
    int nc = 6;
    unsigned mask = 0u;
    int* out = &g_nn[it][b][i][0];
    for (int sel = 0; sel < NG; sel++) {
        unsigned bv = c0; int bj = j0;
#pragma unroll
        for (int off = 16; off; off >>= 1) {
            unsigned ov = __shfl_xor_sync(0xffffffffu, bv, off);
            int      oj = __shfl_xor_sync(0xffffffffu, bj, off);
            if (ov > bv || (ov == bv && oj < bj)) { bv = ov; bj = oj; }
        }
        if (lane == 0) out[sel] = bj;
        if ((bj & 31) == lane) {
            mask |= 1u << (bj >> 5);
            c0 = c1; j0 = j1; c1 = c2; j1 = j2; c2 = c3; j2 = j3;
            c3 = c4; j3 = j4; c4 = c5; j4 = j5; c5 = 0u; j5 = 0;
            if (--nc == 0) {
                c0 = c1 = c2 = c3 = c4 = c5 = 0u;
                j0 = j1 = j2 = j3 = j4 = j5 = 0;
                for (int t = 0; t < 32; t++) {
                    if ((mask >> t) & 1u) continue;
                    int jj = lane + t * 32;
                    unsigned uk; KEYFOR(jj, uk);
                    INSERT6(uk, jj);
                }
                int rem = 32 - __popc(mask);
                nc = rem < 6 ? rem : 6;
                if (nc == 0) nc = 1000;
            }
        }
        __syncwarp();
    }
#undef KEYFOR
#undef INSERT6
}

// ---------------- weighted Kabsch via f32 one-sided Jacobi SVD ----------------
__global__ void kabsch_kernel() {
    int id = blockIdx.x * blockDim.x + threadIdx.x;
    if (id >= NIT * NB * NS) return;
    int it = id >> 13, rr = id & 8191;
    int b = rr >> 10, s = rr & 1023;
    const int* nn = &g_nn[it][b][s][0];
    const float4* __restrict__ S = &g_s4[it][b][0];
    const float4* __restrict__ C = &g_c4[it][b][0];
    float smx = 0, smy = 0, smz = 0, cmx = 0, cmy = 0, cmz = 0, wsum = 0;
    for (int g = 0; g < NG; g++) {
        int j = nn[g];
        float4 sp = S[j], cp = C[j];
        smx += sp.x; smy += sp.y; smz += sp.z;
        cmx += cp.x; cmy += cp.y; cmz += cp.z;
        wsum += sp.w;
    }
    const float inv30 = 1.0f / 30.0f;
    smx *= inv30; smy *= inv30; smz *= inv30;
    cmx *= inv30; cmy *= inv30; cmz *= inv30;
    float winv = 1.0f / wsum;
    float H[3][3] = {};
    for (int g = 0; g < NG; g++) {
        int j = nn[g];
        float4 sp = S[j], cp = C[j];
        float wn = sp.w * winv;
        float ax = sp.x - smx, ay = sp.y - smy, az = sp.z - smz;
        float bx = cp.x - cmx, by = cp.y - cmy, bz = cp.z - cmz;
        float wax = wn * ax, way = wn * ay, waz = wn * az;
        H[0][0] += wax * bx; H[0][1] += wax * by; H[0][2] += wax * bz;
        H[1][0] += way * bx; H[1][1] += way * by; H[1][2] += way * bz;
        H[2][0] += waz * bx; H[2][1] += waz * by; H[2][2] += waz * bz;
    }
    float W[3][3], V[3][3];
    for (int r = 0; r < 3; r++) for (int c = 0; c < 3; c++) { W[r][c] = H[r][c]; V[r][c] = (r == c) ? 1.f : 0.f; }
    const int PP[3] = {0, 0, 1}, QQ[3] = {1, 2, 2};
    for (int sweep = 0; sweep < 7; sweep++) {
        for (int pi = 0; pi < 3; pi++) {
            int p = PP[pi], q = QQ[pi];
            float app = W[0][p] * W[0][p] + W[1][p] * W[1][p] + W[2][p] * W[2][p];
            float aqq = W[0][q] * W[0][q] + W[1][q] * W[1][q] + W[2][q] * W[2][q];
            float apq = W[0][p] * W[0][q] + W[1][p] * W[1][q] + W[2][p] * W[2][q];
            if (fabsf(apq) < 1e-25f) continue;
            float zeta = (aqq - app) / (2.0f * apq);
            float t = copysignf(1.0f, zeta) / (fabsf(zeta) + sqrtf(1.0f + zeta * zeta));
            float cs = 1.0f / sqrtf(1.0f + t * t);
            float sn = cs * t;
            for (int r = 0; r < 3; r++) {
                float wp = W[r][p], wq = W[r][q];
                W[r][p] = cs * wp - sn * wq;
                W[r][q] = sn * wp + cs * wq;
                float vp = V[r][p], vq = V[r][q];
                V[r][p] = cs * vp - sn * vq;
                V[r][q] = sn * vp + cs * vq;
            }
        }
    }
    float n0 = W[0][0] * W[0][0] + W[1][0] * W[1][0] + W[2][0] * W[2][0];
    float n1 = W[0][1] * W[0][1] + W[1][1] * W[1][1] + W[2][1] * W[2][1];
    float n2 = W[0][2] * W[0][2] + W[1][2] * W[1][2] + W[2][2] * W[2][2];
    int i0 = 0, i1 = 1, i2 = 2;
    if (n1 > n0) { float tn = n0; n0 = n1; n1 = tn; int ti = i0; i0 = i1; i1 = ti; }
    if (n2 > n0) { float tn = n0; n0 = n2; n2 = tn; int ti = i0; i0 = i2; i2 = ti; }
    if (n2 > n1) { float tn = n1; n1 = n2; n2 = tn; int ti = i1; i1 = i2; i2 = ti; }
    float u1x = W[0][i0], u1y = W[1][i0], u1z = W[2][i0];
    float s1i = 1.0f / sqrtf(fmaxf(n0, 1e-30f));
    u1x *= s1i; u1y *= s1i; u1z *= s1i;
    float u2x = W[0][i1], u2y = W[1][i1], u2z = W[2][i1];
    float dp = u1x * u2x + u1y * u2y + u1z * u2z;
    u2x -= dp * u1x; u2y -= dp * u1y; u2z -= dp * u1z;
    float s2i = 1.0f / sqrtf(fmaxf(u2x * u2x + u2y * u2y + u2z * u2z, 1e-30f));
    u2x *= s2i; u2y *= s2i; u2z *= s2i;
    float u3x = u1y * u2z - u1z * u2y;
    float u3y = u1z * u2x - u1x * u2z;
    float u3z = u1x * u2y - u1y * u2x;
    float v1x = V[0][i0], v1y = V[1][i0], v1z = V[2][i0];
    float v2x = V[0][i1], v2y = V[1][i1], v2z = V[2][i1];
    float v3x = v1y * v2z - v1z * v2y;
    float v3y = v1z * v2x - v1x * v2z;
    float v3z = v1x * v2y - v1y * v2x;
    float R[3][3];
    R[0][0] = v1x * u1x + v2x * u2x + v3x * u3x;
    R[0][1] = v1x * u1y + v2x * u2y + v3x * u3y;
    R[0][2] = v1x * u1z + v2x * u2z + v3x * u3z;
    R[1][0] = v1y * u1x + v2y * u2x + v3y * u3x;
    R[1][1] = v1y * u1y + v2y * u2y + v3y * u3y;
    R[1][2] = v1y * u1z + v2y * u2z + v3y * u3z;
    R[2][0] = v1z * u1x + v2z * u2x + v3z * u3x;
    R[2][1] = v1z * u1y + v2z * u2y + v3z * u3y;
    R[2][2] = v1z * u1z + v2z * u2z + v3z * u3z;
    float tx = -(R[0][0] * smx + R[0][1] * smy + R[0][2] * smz) + cmx;
    float ty = -(R[1][0] * smx + R[1][1] * smy + R[1][2] * smz) + cmy;
    float tz = -(R[2][0] * smx + R[2][1] * smy + R[2][2] * smz) + cmz;
    float* o = &g_Rt[it][b][s][0];
    o[0] = R[0][0]; o[1] = R[0][1]; o[2] = R[0][2];
    o[3] = R[1][0]; o[4] = R[1][1]; o[5] = R[1][2];
    o[6] = R[2][0]; o[7] = R[2][1]; o[8] = R[2][2];
    o[9] = tx; o[10] = ty; o[11] = tz;
}

// ---------------- fitness: one seed per thread, packed f32x2, 2 pts/iter ----
__global__ void __launch_bounds__(128) fitness_kernel() {
    int blk = blockIdx.x;              // 0..639
    int it = blk >> 6;
    int q = blk & 63;
    int b = q >> 3;
    int s = ((q & 7) << 7) + threadIdx.x;
    int tid = threadIdx.x;
    const float4* rt4 = (const float4*)&g_Rt[it][b][s][0];
    float4 A = rt4[0], B4 = rt4[1], C4 = rt4[2];
    // A=(R00,R01,R02,R10) B4=(R11,R12,R20,R21) C4=(R22,tx,ty,tz)
    ull q00 = pk2(A.x),  q01 = pk2(A.y),  q02 = pk2(A.z);
    ull q10 = pk2(A.w),  q11 = pk2(B4.x), q12 = pk2(B4.y);
    ull q20 = pk2(B4.z), q21 = pk2(B4.w), q22 = pk2(C4.x);
    ull qtx = pk2(C4.y), qty = pk2(C4.z), qtz = pk2(C4.w);
    __shared__ float ssx[256], ssy[256], ssz[256];
    __shared__ float ntx[256], nty[256], ntz[256];   // negated tgt
    int cnt = 0;
    for (int cb = 0; cb < NPTS; cb += 256) {
        __syncthreads();
        for (int p = tid; p < 256; p += 128) {
            float4 P = g_src4[b][cb + p];
            ssx[p] = P.x; ssy[p] = P.y; ssz[p] = P.z;
            float4 T = g_tgt4[b][cb + p];
            ntx[p] = -T.x; nty[p] = -T.y; ntz[p] = -T.z;
        }
        __syncthreads();
#pragma unroll 4
        for (int p = 0; p < 128; p++) {
            ull Px = *(const ull*)&ssx[2 * p];
            ull Py = *(const ull*)&ssy[2 * p];
            ull Pz = *(const ull*)&ssz[2 * p];
            ull Tx = *(const ull*)&ntx[2 * p];
            ull Ty = *(const ull*)&nty[2 * p];
            ull Tz = *(const ull*)&ntz[2 * p];
            ull ex, ey, ez;
            // px = fma(R00,Px, fma(R01,Py, fma(R02,Pz,tx)));  dx = px + (-Tx)
            FMA2(ex, q02, Pz, qtx); FMA2(ex, q01, Py, ex); FMA2(ex, q00, Px, ex); ADD2(ex, ex, Tx);
            FMA2(ey, q12, Pz, qty); FMA2(ey, q11, Py, ey); FMA2(ey, q10, Px, ey); ADD2(ey, ey, Ty);
            FMA2(ez, q22, Pz, qtz); FMA2(ez, q21, Py, ez); FMA2(ez, q20, Px, ez); ADD2(ez, ez, Tz);
            ull d2; MUL2(d2, ez, ez); FMA2(d2, ey, ey, d2); FMA2(d2, ex, ex, d2);
            float lo, hi; unpk(lo, hi, d2);
            cnt += (lo < 0.01f) ? 1 : 0;
            cnt += (hi < 0.01f) ? 1 : 0;
        }
    }
    g_cnt[it][b][s] = cnt;
}

// ---------------- final selection across all iterations ----------------
__global__ void select_kernel(float* __restrict__ out) {
    int tid = threadIdx.x, b = tid >> 5, lane = tid & 31;
    __shared__ int bc_s[8], bs_s[8];
    __shared__ int flag;
    __shared__ float dist_s;
    if (tid == 0) dist_s = 1e8f;
    __syncthreads();
    for (int it = 0; it < NIT; it++) {
        int bc = -1, bs = 0;
        for (int j = lane; j < NS; j += 32) {
            int c = g_cnt[it][b][j];
            if (c > bc) { bc = c; bs = j; }
        }
        for (int off = 16; off; off >>= 1) {
            int oc = __shfl_xor_sync(0xffffffffu, bc, off);
            int os = __shfl_xor_sync(0xffffffffu, bs, off);
            if (oc > bc || (oc == bc && os < bs)) { bc = oc; bs = os; }
        }
        if (lane == 0) { bc_s[b] = bc; bs_s[b] = bs; }
        __syncthreads();
        if (tid == 0) {
            float s = 0.f;
            for (int i = 0; i < 8; i++) s += (float)bc_s[i] * (1.0f / 2048.0f);
            float vv = s * 0.125f;
            flag = (vv < dist_s) ? 1 : 0;
            if (flag) dist_s = vv;
        }
        __syncthreads();
        if (flag) {
            if (tid < 72) {
                int bb = tid / 9, e = tid % 9;
                out[tid] = g_Rt[it][bb][bs_s[bb]][e];
            } else if (tid < 96) {
                int qq = tid - 72, bb = qq / 3, e = qq % 3;
                out[tid] = g_Rt[it][bb][bs_s[bb]][9 + e];
            }
        }
        __syncthreads();
    }
}

// ---------------- launch ----------------
extern "C" void kernel_launch(void* const* d_in, const int* in_sizes, int n_in,
                              void* d_out, int out_size) {
    int wi = 2;
    if (n_in >= 3) {
        if (in_sizes[0] == NB * NPTS) wi = 0;
        else if (in_sizes[1] == NB * NPTS) wi = 1;
        else wi = 2;
    }
    int si = (wi == 0) ? 1 : 0;
    int ti = si + 1; if (ti == wi) ti++;
    const float* src = (const float*)d_in[si];
    const float* tgt = (const float*)d_in[ti];
    const float* wts = (const float*)d_in[wi];
    float* out = (float*)d_out;

    Keys K;
    for (int it = 0; it < NIT; it++) {
        unsigned f0, f1;
        tf2x32(0u, 42u, 0u, (unsigned)it, f0, f1);
        tf2x32(f0, f1, 0u, 0u, K.sa[it], K.sb[it]);
        tf2x32(f0, f1, 0u, 1u, K.na[it], K.nb[it]);
    }

    softmax_kernel<<<NB, 256>>>(wts, src, tgt);
    seed_kernel<<<NIT * NB, 1024>>>(K);
    nn_kernel<<<NIT * 1024, 256>>>(K);
    kabsch_kernel<<<640, 128>>>();
    fitness_kernel<<<NIT * 64, 128>>>();
    select_kernel<<<1, 256>>>(out);
}

// round 13
// speedup vs baseline: 2.4224x; 1.1269x over previous
#include <cuda_runtime.h>
#include <math.h>

#define NB    8
#define NPTS  2048
#define NS    1024
#define NG    30
#define NIT   10

typedef unsigned long long ull;

// ---------------- persistent device scratch (no allocations) ----------------
__device__ float  g_w[NB][NPTS];
__device__ float  g_logw[NB][NPTS];
__device__ float4 g_src4[NB][NPTS];
__device__ float4 g_tgt4[NB][NPTS];
__device__ float4 g_s4[NIT][NB][NS];
__device__ float4 g_c4[NIT][NB][NS];
__device__ int    g_nn[NIT][NB][NS][NG];
__device__ float  g_Rt[NIT][NB][NS][12];
__device__ int    g_cnt[NIT][NB][NS];
__device__ unsigned g_best[NIT][NB];

struct Keys {
    unsigned sa[NIT], sb[NIT];
    unsigned na[NIT], nb[NIT];
};

// ---------------- threefry-2x32 (JAX), host+device ----------------
__host__ __device__ __forceinline__ void tf2x32(unsigned k0, unsigned k1,
                                                unsigned x0, unsigned x1,
                                                unsigned& o0, unsigned& o1) {
    unsigned ks2 = k0 ^ k1 ^ 0x1BD11BDAu;
    x0 += k0; x1 += k1;
#define TF_RND(r) { x0 += x1; x1 = (x1 << (r)) | (x1 >> (32 - (r))); x1 ^= x0; }
    TF_RND(13) TF_RND(15) TF_RND(26) TF_RND(6)
    x0 += k1;  x1 += ks2 + 1u;
    TF_RND(17) TF_RND(29) TF_RND(16) TF_RND(24)
    x0 += ks2; x1 += k0 + 2u;
    TF_RND(13) TF_RND(15) TF_RND(26) TF_RND(6)
    x0 += k0;  x1 += k1 + 3u;
    TF_RND(17) TF_RND(29) TF_RND(16) TF_RND(24)
    x0 += k1;  x1 += ks2 + 4u;
    TF_RND(13) TF_RND(15) TF_RND(26) TF_RND(6)
    x0 += ks2; x1 += k0 + 5u;
#undef TF_RND
    o0 = x0; o1 = x1;
}

__device__ __forceinline__ unsigned rbits32(unsigned ka, unsigned kb, unsigned m) {
    unsigned o0, o1;
    tf2x32(ka, kb, 0u, m, o0, o1);
    return o0 ^ o1;
}

__device__ __forceinline__ float gumbel_from_bits(unsigned bits) {
    float f = __uint_as_float((bits >> 9) | 0x3f800000u) - 1.0f;
    float u = fmaxf(1e-9f, f + 1e-9f);
    return -logf(-logf(u));
}

__device__ __forceinline__ unsigned float_mono(float x) {
    unsigned u = __float_as_uint(x);
    return (u & 0x80000000u) ? ~u : (u | 0x80000000u);
}

// ---------------- packed f32x2 helpers (per-element IEEE identical) ----------
#define FMA2(d,a,b,c) asm("fma.rn.f32x2 %0, %1, %2, %3;" : "=l"(d) : "l"(a), "l"(b), "l"(c))
#define ADD2(d,a,b)   asm("add.rn.f32x2 %0, %1, %2;" : "=l"(d) : "l"(a), "l"(b))
#define MUL2(d,a,b)   asm("mul.rn.f32x2 %0, %1, %2;" : "=l"(d) : "l"(a), "l"(b))

__device__ __forceinline__ ull pk2(float v) {
    ull r; asm("mov.b64 %0, {%1, %1};" : "=l"(r) : "f"(v)); return r;
}
__device__ __forceinline__ void unpk(float& lo, float& hi, ull d) {
    asm("mov.b64 {%0, %1}, %2;" : "=f"(lo), "=f"(hi) : "l"(d));
}

// ---------------- softmax + log + pack src/tgt as float4 ----------------
__global__ void softmax_kernel(const float* __restrict__ win,
                               const float* __restrict__ src,
                               const float* __restrict__ tgt) {
    int b = blockIdx.x, tid = threadIdx.x;
    __shared__ float red[256];
    float mx = -3.402823466e38f;
    for (int n = tid; n < NPTS; n += 256) {
        float x = win[b * NPTS + n];
        if (isnan(x)) x = 1e-7f;
        if (isinf(x)) x = 1.0f;
        mx = fmaxf(mx, x);
    }
    red[tid] = mx; __syncthreads();
    for (int o = 128; o > 0; o >>= 1) { if (tid < o) red[tid] = fmaxf(red[tid], red[tid + o]); __syncthreads(); }
    mx = red[0]; __syncthreads();
    float s = 0.f;
    for (int n = tid; n < NPTS; n += 256) {
        float x = win[b * NPTS + n];
        if (isnan(x)) x = 1e-7f;
        if (isinf(x)) x = 1.0f;
        float e = expf(x - mx);
        g_w[b][n] = e;
        s += e;
    }
    red[tid] = s; __syncthreads();
    for (int o = 128; o > 0; o >>= 1) { if (tid < o) red[tid] += red[tid + o]; __syncthreads(); }
    s = red[0];
    for (int n = tid; n < NPTS; n += 256) {
        float wv = g_w[b][n] / s;
        g_w[b][n] = wv;
        g_logw[b][n] = logf(wv);
        g_src4[b][n] = make_float4(src[(b * 3 + 0) * NPTS + n],
                                   src[(b * 3 + 1) * NPTS + n],
                                   src[(b * 3 + 2) * NPTS + n], 0.f);
        g_tgt4[b][n] = make_float4(tgt[(b * 3 + 0) * NPTS + n],
                                   tgt[(b * 3 + 1) * NPTS + n],
                                   tgt[(b * 3 + 2) * NPTS + n], 0.f);
    }
}

// ---------------- seed selection (all iterations): bitonic sort ----------------
__global__ void seed_kernel(Keys K) {
    int it = blockIdx.x >> 3, b = blockIdx.x & 7;
    int tid = threadIdx.x; // 1024 threads
    unsigned ka = K.sa[it], kb = K.sb[it];
    __shared__ unsigned long long arr[NPTS];
    for (int n = tid; n < NPTS; n += 1024) {
        unsigned m = (unsigned)(b * NPTS + n);
        float key = g_logw[b][n] + gumbel_from_bits(rbits32(ka, kb, m));
        unsigned uk = float_mono(key);
        arr[n] = ((unsigned long long)(~uk) << 32) | (unsigned)n;
    }
    __syncthreads();
    for (int k = 2; k <= NPTS; k <<= 1) {
        for (int j = k >> 1; j > 0; j >>= 1) {
            for (int i = tid; i < NPTS; i += 1024) {
                int ixj = i ^ j;
                if (ixj > i) {
                    unsigned long long a = arr[i], c = arr[ixj];
                    bool up = ((i & k) == 0);
                    if ((a > c) == up) { arr[i] = c; arr[ixj] = a; }
                }
            }
            __syncthreads();
        }
    }
    for (int s0 = tid; s0 < NS; s0 += 1024) {
        int j = (int)(arr[s0] & 0xFFFFFFFFull);
        float4 sp = g_src4[b][j];
        sp.w = g_w[b][j];
        g_s4[it][b][s0] = sp;
        g_c4[it][b][s0] = g_tgt4[b][j];
    }
}

// ---------------- group selection: top-30 per row, warp per row ----------------
// Branchless per-lane top-6 cache + predicated pop + REDUX warp argmax.
// All key VALUES computed identically to prior passing version; only control
// flow / reduction mechanics changed (order-preserving, tie-stable).
__global__ void __launch_bounds__(256) nn_kernel(Keys K) {
    int w = threadIdx.x >> 5, lane = threadIdx.x & 31;
    int r = blockIdx.x * 8 + w;
    int it = r >> 13;
    int rr = r & 8191;
    int b = rr >> 10, i = rr & 1023;
    unsigned ka = K.na[it], kb = K.nb[it];
    const float4* __restrict__ S = &g_s4[it][b][0];
    const float4* __restrict__ C = &g_c4[it][b][0];
    float4 si = S[i], ci = C[i];

    unsigned c0 = 0, c1 = 0, c2 = 0, c3 = 0, c4 = 0, c5 = 0;
    int j0 = 0, j1 = 0, j2 = 0, j3 = 0, j4 = 0, j5 = 0;

#define KEYFOR(jv, ukv) { \
    float4 sj = S[jv], cjv = C[jv]; \
    float dx = si.x - sj.x, dy = si.y - sj.y, dz = si.z - sj.z; \
    float ex = ci.x - cjv.x, ey = ci.y - cjv.y, ez = ci.z - cjv.z; \
    float d1 = sqrtf(__fmaf_rn(dx, dx, __fmaf_rn(dy, dy, __fmul_rn(dz, dz)))); \
    float d2 = sqrtf(__fmaf_rn(ex, ex, __fmaf_rn(ey, ey, __fmul_rn(ez, ez)))); \
    float dd = d1 - d2; \
    float lc = fmaxf(-__fmul_rn(__fmul_rn(dd, dd), 100.0f), -2.3025851f); \
    ukv = float_mono(lc + gumbel_from_bits(rbits32(ka, kb, (unsigned)rr * 1024u + (unsigned)(jv)))); \
}

// Branchless sorted insert into (c0>=c1>=...>=c5); strict > keeps earlier
// (lower-j) entries ahead on ties. Update slots 5->0 using old upper values.
#define BINSERT6(uk, jn) { \
    unsigned _u = (uk); int _j = (jn); \
    bool g0 = _u > c0, g1 = _u > c1, g2 = _u > c2; \
    bool g3 = _u > c3, g4 = _u > c4, g5 = _u > c5; \
    c5 = g5 ? (g4 ? c4 : _u) : c5;  j5 = g5 ? (g4 ? j4 : _j) : j5; \
    c4 = g4 ? (g3 ? c3 : _u) : c4;  j4 = g4 ? (g3 ? j3 : _j) : j4; \
    c3 = g3 ? (g2 ? c2 : _u) : c3;  j3 = g3 ? (g2 ? j2 : _j) : j3; \
    c2 = g2 ? (g1 ? c1 : _u) : c2;  j2 = g2 ? (g1 ? j1 : _j) : j2; \
    c1 = g1 ? (g0 ? c0 : _u) : c1;  j1 = g1 ? (g0 ? j0 : _j) : j1; \
    c0 = g0 ? _u : c0;              j0 = g0 ? _j : j0; \
}

#pragma unroll 4
    for (int t = 0; t < 32; t++) {
        int j = lane + t * 32;
        unsigned uk; KEYFOR(j, uk);
        BINSERT6(uk, j);
    }
    int nc = 6;
    unsigned mask = 0u;
    int* out = &g_nn[it][b][i][0];
    for (int sel = 0; sel < NG; sel++) {
        unsigned m = __reduce_max_sync(0xffffffffu, c0);
        unsigned jj = (c0 == m) ? (unsigned)j0 : 0xFFFFFFFFu;
        int bj = (int)__reduce_min_sync(0xffffffffu, jj);
        if (lane == 0) out[sel] = bj;
        // predicated pop (no divergence)
        bool pop = ((bj & 31) == lane);
        mask |= pop ? (1u << (bj >> 5)) : 0u;
        c0 = pop ? c1 : c0; j0 = pop ? j1 : j0;
        c1 = pop ? c2 : c1; j1 = pop ? j2 : j1;
        c2 = pop ? c3 : c2; j2 = pop ? j3 : j2;
        c3 = pop ? c4 : c3; j3 = pop ? j4 : j3;
        c4 = pop ? c5 : c4; j4 = pop ? j5 : j4;
        c5 = pop ? 0u : c5; j5 = pop ? 0  : j5;
        nc -= (int)pop;
        if (nc == 0) {   // cold: rebuild top-6 of this lane's unconsumed keys
            c0 = c1 = c2 = c3 = c4 = c5 = 0u;
            j0 = j1 = j2 = j3 = j4 = j5 = 0;
            for (int t = 0; t < 32; t++) {
                if ((mask >> t) & 1u) continue;
                int jn = lane + t * 32;
                unsigned uk; KEYFOR(jn, uk);
                BINSERT6(uk, jn);
            }
            int rem = 32 - __popc(mask);
            nc = rem < 6 ? rem : 6;
            if (nc == 0) nc = 1000;
        }
    }
#undef KEYFOR
#undef BINSERT6
}

// ---------------- weighted Kabsch via f32 one-sided Jacobi SVD ----------------
__global__ void kabsch_kernel() {
    int id = blockIdx.x * blockDim.x + threadIdx.x;
    if (id >= NIT * NB * NS) return;
    int it = id >> 13, rr = id & 8191;
    int b = rr >> 10, s = rr & 1023;
    const int* nn = &g_nn[it][b][s][0];
    const float4* __restrict__ S = &g_s4[it][b][0];
    const float4* __restrict__ C = &g_c4[it][b][0];
    float smx = 0, smy = 0, smz = 0, cmx = 0, cmy = 0, cmz = 0, wsum = 0;
    for (int g = 0; g < NG; g++) {
        int j = nn[g];
        float4 sp = S[j], cp = C[j];
        smx += sp.x; smy += sp.y; smz += sp.z;
        cmx += cp.x; cmy += cp.y; cmz += cp.z;
        wsum += sp.w;
    }
    const float inv30 = 1.0f / 30.0f;
    smx *= inv30; smy *= inv30; smz *= inv30;
    cmx *= inv30; cmy *= inv30; cmz *= inv30;
    float winv = 1.0f / wsum;
    float H[3][3] = {};
    for (int g = 0; g < NG; g++) {
        int j = nn[g];
        float4 sp = S[j], cp = C[j];
        float wn = sp.w * winv;
        float ax = sp.x - smx, ay = sp.y - smy, az = sp.z - smz;
        float bx = cp.x - cmx, by = cp.y - cmy, bz = cp.z - cmz;
        float wax = wn * ax, way = wn * ay, waz = wn * az;
        H[0][0] += wax * bx; H[0][1] += wax * by; H[0][2] += wax * bz;
        H[1][0] += way * bx; H[1][1] += way * by; H[1][2] += way * bz;
        H[2][0] += waz * bx; H[2][1] += waz * by; H[2][2] += waz * bz;
    }
    float W[3][3], V[3][3];
    for (int r = 0; r < 3; r++) for (int c = 0; c < 3; c++) { W[r][c] = H[r][c]; V[r][c] = (r == c) ? 1.f : 0.f; }
    const int PP[3] = {0, 0, 1}, QQ[3] = {1, 2, 2};
    for (int sweep = 0; sweep < 7; sweep++) {
        for (int pi = 0; pi < 3; pi++) {
            int p = PP[pi], q = QQ[pi];
            float app = W[0][p] * W[0][p] + W[1][p] * W[1][p] + W[2][p] * W[2][p];
            float aqq = W[0][q] * W[0][q] + W[1][q] * W[1][q] + W[2][q] * W[2][q];
            float apq = W[0][p] * W[0][q] + W[1][p] * W[1][q] + W[2][p] * W[2][q];
            if (fabsf(apq) < 1e-25f) continue;
            float zeta = (aqq - app) / (2.0f * apq);
            float t = copysignf(1.0f, zeta) / (fabsf(zeta) + sqrtf(1.0f + zeta * zeta));
            float cs = 1.0f / sqrtf(1.0f + t * t);
            float sn = cs * t;
            for (int r = 0; r < 3; r++) {
                float wp = W[r][p], wq = W[r][q];
                W[r][p] = cs * wp - sn * wq;
                W[r][q] = sn * wp + cs * wq;
                float vp = V[r][p], vq = V[r][q];
                V[r][p] = cs * vp - sn * vq;
                V[r][q] = sn * vp + cs * vq;
            }
        }
    }
    float n0 = W[0][0] * W[0][0] + W[1][0] * W[1][0] + W[2][0] * W[2][0];
    float n1 = W[0][1] * W[0][1] + W[1][1] * W[1][1] + W[2][1] * W[2][1];
    float n2 = W[0][2] * W[0][2] + W[1][2] * W[1][2] + W[2][2] * W[2][2];
    int i0 = 0, i1 = 1, i2 = 2;
    if (n1 > n0) { float tn = n0; n0 = n1; n1 = tn; int ti = i0; i0 = i1; i1 = ti; }
    if (n2 > n0) { float tn = n0; n0 = n2; n2 = tn; int ti = i0; i0 = i2; i2 = ti; }
    if (n2 > n1) { float tn = n1; n1 = n2; n2 = tn; int ti = i1; i1 = i2; i2 = ti; }
    float u1x = W[0][i0], u1y = W[1][i0], u1z = W[2][i0];
    float s1i = 1.0f / sqrtf(fmaxf(n0, 1e-30f));
    u1x *= s1i; u1y *= s1i; u1z *= s1i;
    float u2x = W[0][i1], u2y = W[1][i1], u2z = W[2][i1];
    float dp = u1x * u2x + u1y * u2y + u1z * u2z;
    u2x -= dp * u1x; u2y -= dp * u1y; u2z -= dp * u1z;
    float s2i = 1.0f / sqrtf(fmaxf(u2x * u2x + u2y * u2y + u2z * u2z, 1e-30f));
    u2x *= s2i; u2y *= s2i; u2z *= s2i;
    float u3x = u1y * u2z - u1z * u2y;
    float u3y = u1z * u2x - u1x * u2z;
    float u3z = u1x * u2y - u1y * u2x;
    float v1x = V[0][i0], v1y = V[1][i0], v1z = V[2][i0];
    float v2x = V[0][i1], v2y = V[1][i1], v2z = V[2][i1];
    float v3x = v1y * v2z - v1z * v2y;
    float v3y = v1z * v2x - v1x * v2z;
    float v3z = v1x * v2y - v1y * v2x;
    float R[3][3];
    R[0][0] = v1x * u1x + v2x * u2x + v3x * u3x;
    R[0][1] = v1x * u1y + v2x * u2y + v3x * u3y;
    R[0][2] = v1x * u1z + v2x * u2z + v3x * u3z;
    R[1][0] = v1y * u1x + v2y * u2x + v3y * u3x;
    R[1][1] = v1y * u1y + v2y * u2y + v3y * u3y;
    R[1][2] = v1y * u1z + v2y * u2z + v3y * u3z;
    R[2][0] = v1z * u1x + v2z * u2x + v3z * u3x;
    R[2][1] = v1z * u1y + v2z * u2y + v3z * u3y;
    R[2][2] = v1z * u1z + v2z * u2z + v3z * u3z;
    float tx = -(R[0][0] * smx + R[0][1] * smy + R[0][2] * smz) + cmx;
    float ty = -(R[1][0] * smx + R[1][1] * smy + R[1][2] * smz) + cmy;
    float tz = -(R[2][0] * smx + R[2][1] * smy + R[2][2] * smz) + cmz;
    float* o = &g_Rt[it][b][s][0];
    o[0] = R[0][0]; o[1] = R[0][1]; o[2] = R[0][2];
    o[3] = R[1][0]; o[4] = R[1][1]; o[5] = R[1][2];
    o[6] = R[2][0]; o[7] = R[2][1]; o[8] = R[2][2];
    o[9] = tx; o[10] = ty; o[11] = tz;
}

// ---------------- fitness: one seed per thread, packed f32x2, 2 pts/iter ----
__global__ void __launch_bounds__(128) fitness_kernel() {
    int blk = blockIdx.x;              // 0..639
    int it = blk >> 6;
    int q = blk & 63;
    int b = q >> 3;
    int s = ((q & 7) << 7) + threadIdx.x;
    int tid = threadIdx.x;
    const float4* rt4 = (const float4*)&g_Rt[it][b][s][0];
    float4 A = rt4[0], B4 = rt4[1], C4 = rt4[2];
    ull q00 = pk2(A.x),  q01 = pk2(A.y),  q02 = pk2(A.z);
    ull q10 = pk2(A.w),  q11 = pk2(B4.x), q12 = pk2(B4.y);
    ull q20 = pk2(B4.z), q21 = pk2(B4.w), q22 = pk2(C4.x);
    ull qtx = pk2(C4.y), qty = pk2(C4.z), qtz = pk2(C4.w);
    __shared__ float ssx[256], ssy[256], ssz[256];
    __shared__ float ntx[256], nty[256], ntz[256];
    int cnt = 0;
    for (int cb = 0; cb < NPTS; cb += 256) {
        __syncthreads();
        for (int p = tid; p < 256; p += 128) {
            float4 P = g_src4[b][cb + p];
            ssx[p] = P.x; ssy[p] = P.y; ssz[p] = P.z;
            float4 T = g_tgt4[b][cb + p];
            ntx[p] = -T.x; nty[p] = -T.y; ntz[p] = -T.z;
        }
        __syncthreads();
#pragma unroll 4
        for (int p = 0; p < 128; p++) {
            ull Px = *(const ull*)&ssx[2 * p];
            ull Py = *(const ull*)&ssy[2 * p];
            ull Pz = *(const ull*)&ssz[2 * p];
            ull Tx = *(const ull*)&ntx[2 * p];
            ull Ty = *(const ull*)&nty[2 * p];
            ull Tz = *(const ull*)&ntz[2 * p];
            ull ex, ey, ez;
            FMA2(ex, q02, Pz, qtx); FMA2(ex, q01, Py, ex); FMA2(ex, q00, Px, ex); ADD2(ex, ex, Tx);
            FMA2(ey, q12, Pz, qty); FMA2(ey, q11, Py, ey); FMA2(ey, q10, Px, ey); ADD2(ey, ey, Ty);
            FMA2(ez, q22, Pz, qtz); FMA2(ez, q21, Py, ez); FMA2(ez, q20, Px, ez); ADD2(ez, ez, Tz);
            ull d2; MUL2(d2, ez, ez); FMA2(d2, ey, ey, d2); FMA2(d2, ex, ex, d2);
            float lo, hi; unpk(lo, hi, d2);
            cnt += (lo < 0.01f) ? 1 : 0;
            cnt += (hi < 0.01f) ? 1 : 0;
        }
    }
    g_cnt[it][b][s] = cnt;
}

// ---------------- per-(it,b) argmax: packed (count<<10)|(1023-j) ----------------
__global__ void argmax_kernel() {
    int idx = blockIdx.x;              // 0..79
    int it = idx >> 3, b = idx & 7;
    int tid = threadIdx.x;             // 256
    unsigned best = 0;
    for (int k = 0; k < 4; k++) {
        int j = tid + k * 256;
        unsigned c = (unsigned)g_cnt[it][b][j];
        unsigned packed = (c << 10) | (1023u - (unsigned)j);
        if (packed > best) best = packed;
    }
    best = __reduce_max_sync(0xffffffffu, best);
    __shared__ unsigned wb[8];
    if ((tid & 31) == 0) wb[tid >> 5] = best;
    __syncthreads();
    if (tid == 0) {
        unsigned m = wb[0];
        for (int wv = 1; wv < 8; wv++) m = max(m, wb[wv]);
        g_best[it][b] = m;
    }
}

// ---------------- final selection across all iterations ----------------
__global__ void select_kernel(float* __restrict__ out) {
    int tid = threadIdx.x;
    __shared__ int bc_s[8], bs_s[8];
    __shared__ int flag;
    __shared__ float dist_s;
    if (tid == 0) dist_s = 1e8f;
    __syncthreads();
    for (int it = 0; it < NIT; it++) {
        if (tid < 8) {
            unsigned p = g_best[it][tid];
            bc_s[tid] = (int)(p >> 10);
            bs_s[tid] = 1023 - (int)(p & 1023u);
        }
        __syncthreads();
        if (tid == 0) {
            float s = 0.f;
            for (int i = 0; i < 8; i++) s += (float)bc_s[i] * (1.0f / 2048.0f);
            float vv = s * 0.125f;
            flag = (vv < dist_s) ? 1 : 0;
            if (flag) dist_s = vv;
        }
        __syncthreads();
        if (flag) {
            if (tid < 72) {
                int bb = tid / 9, e = tid % 9;
                out[tid] = g_Rt[it][bb][bs_s[bb]][e];
            } else if (tid < 96) {
                int qq = tid - 72, bb = qq / 3, e = qq % 3;
                out[tid] = g_Rt[it][bb][bs_s[bb]][9 + e];
            }
        }
        __syncthreads();
    }
}

// ---------------- launch ----------------
extern "C" void kernel_launch(void* const* d_in, const int* in_sizes, int n_in,
                              void* d_out, int out_size) {
    int wi = 2;
    if (n_in >= 3) {
        if (in_sizes[0] == NB * NPTS) wi = 0;
        else if (in_sizes[1] == NB * NPTS) wi = 1;
        else wi = 2;
    }
    int si = (wi == 0) ? 1 : 0;
    int ti = si + 1; if (ti == wi) ti++;
    const float* src = (const float*)d_in[si];
    const float* tgt = (const float*)d_in[ti];
    const float* wts = (const float*)d_in[wi];
    float* out = (float*)d_out;

    Keys K;
    for (int it = 0; it < NIT; it++) {
        unsigned f0, f1;
        tf2x32(0u, 42u, 0u, (unsigned)it, f0, f1);
        tf2x32(f0, f1, 0u, 0u, K.sa[it], K.sb[it]);
        tf2x32(f0, f1, 0u, 1u, K.na[it], K.nb[it]);
    }

    softmax_kernel<<<NB, 256>>>(wts, src, tgt);
    seed_kernel<<<NIT * NB, 1024>>>(K);
    nn_kernel<<<NIT * 1024, 256>>>(K);
    kabsch_kernel<<<640, 128>>>();
    fitness_kernel<<<NIT * 64, 128>>>();
    argmax_kernel<<<NIT * NB, 256>>>();
    select_kernel<<<1, 128>>>(out);
}

// round 16
// speedup vs baseline: 2.4226x; 1.0001x over previous
#include <cuda_runtime.h>
#include <math.h>

#define NB    8
#define NPTS  2048
#define NS    1024
#define NG    30
#define NIT   10

typedef unsigned long long ull;

// ---------------- persistent device scratch (no allocations) ----------------
__device__ float  g_w[NB][NPTS];
__device__ float  g_logw[NB][NPTS];
__device__ float4 g_src4[NB][NPTS];
__device__ float4 g_tgt4[NB][NPTS];
__device__ float4 g_s4[NIT][NB][NS];
__device__ float4 g_c4[NIT][NB][NS];
__device__ int    g_nn[NIT][NB][NS][NG];
__device__ float  g_Rt[NIT][NB][NS][12];
__device__ unsigned g_best[NIT][NB];

struct Keys {
    unsigned sa[NIT], sb[NIT];
    unsigned na[NIT], nb[NIT];
};

// ---------------- threefry-2x32 (JAX), host+device ----------------
__host__ __device__ __forceinline__ void tf2x32(unsigned k0, unsigned k1,
                                                unsigned x0, unsigned x1,
                                                unsigned& o0, unsigned& o1) {
    unsigned ks2 = k0 ^ k1 ^ 0x1BD11BDAu;
    x0 += k0; x1 += k1;
#define TF_RND(r) { x0 += x1; x1 = (x1 << (r)) | (x1 >> (32 - (r))); x1 ^= x0; }
    TF_RND(13) TF_RND(15) TF_RND(26) TF_RND(6)
    x0 += k1;  x1 += ks2 + 1u;
    TF_RND(17) TF_RND(29) TF_RND(16) TF_RND(24)
    x0 += ks2; x1 += k0 + 2u;
    TF_RND(13) TF_RND(15) TF_RND(26) TF_RND(6)
    x0 += k0;  x1 += k1 + 3u;
    TF_RND(17) TF_RND(29) TF_RND(16) TF_RND(24)
    x0 += k1;  x1 += ks2 + 4u;
    TF_RND(13) TF_RND(15) TF_RND(26) TF_RND(6)
    x0 += ks2; x1 += k0 + 5u;
#undef TF_RND
    o0 = x0; o1 = x1;
}

__device__ __forceinline__ unsigned rbits32(unsigned ka, unsigned kb, unsigned m) {
    unsigned o0, o1;
    tf2x32(ka, kb, 0u, m, o0, o1);
    return o0 ^ o1;
}

__device__ __forceinline__ float gumbel_from_bits(unsigned bits) {
    float f = __uint_as_float((bits >> 9) | 0x3f800000u) - 1.0f;
    float u = fmaxf(1e-9f, f + 1e-9f);
    return -logf(-logf(u));
}

__device__ __forceinline__ unsigned float_mono(float x) {
    unsigned u = __float_as_uint(x);
    return (u & 0x80000000u) ? ~u : (u | 0x80000000u);
}

// ---------------- packed f32x2 helpers (per-element IEEE identical) ----------
#define FMA2(d,a,b,c) asm("fma.rn.f32x2 %0, %1, %2, %3;" : "=l"(d) : "l"(a), "l"(b), "l"(c))
#define ADD2(d,a,b)   asm("add.rn.f32x2 %0, %1, %2;" : "=l"(d) : "l"(a), "l"(b))
#define MUL2(d,a,b)   asm("mul.rn.f32x2 %0, %1, %2;" : "=l"(d) : "l"(a), "l"(b))

__device__ __forceinline__ ull pk2(float v) {
    ull r; asm("mov.b64 %0, {%1, %1};" : "=l"(r) : "f"(v)); return r;
}
__device__ __forceinline__ void unpk(float& lo, float& hi, ull d) {
    asm("mov.b64 {%0, %1}, %2;" : "=f"(lo), "=f"(hi) : "l"(d));
}

// ---------------- softmax + log + pack src/tgt + reset g_best ----------------
__global__ void softmax_kernel(const float* __restrict__ win,
                               const float* __restrict__ src,
                               const float* __restrict__ tgt) {
    int b = blockIdx.x, tid = threadIdx.x;
    if (tid < NIT) g_best[tid][b] = 0u;    // reset per replay (graph-safe)
    __shared__ float red[256];
    float mx = -3.402823466e38f;
    for (int n = tid; n < NPTS; n += 256) {
        float x = win[b * NPTS + n];
        if (isnan(x)) x = 1e-7f;
        if (isinf(x)) x = 1.0f;
        mx = fmaxf(mx, x);
    }
    red[tid] = mx; __syncthreads();
    for (int o = 128; o > 0; o >>= 1) { if (tid < o) red[tid] = fmaxf(red[tid], red[tid + o]); __syncthreads(); }
    mx = red[0]; __syncthreads();
    float s = 0.f;
    for (int n = tid; n < NPTS; n += 256) {
        float x = win[b * NPTS + n];
        if (isnan(x)) x = 1e-7f;
        if (isinf(x)) x = 1.0f;
        float e = expf(x - mx);
        g_w[b][n] = e;
        s += e;
    }
    red[tid] = s; __syncthreads();
    for (int o = 128; o > 0; o >>= 1) { if (tid < o) red[tid] += red[tid + o]; __syncthreads(); }
    s = red[0];
    for (int n = tid; n < NPTS; n += 256) {
        float wv = g_w[b][n] / s;
        g_w[b][n] = wv;
        g_logw[b][n] = logf(wv);
        g_src4[b][n] = make_float4(src[(b * 3 + 0) * NPTS + n],
                                   src[(b * 3 + 1) * NPTS + n],
                                   src[(b * 3 + 2) * NPTS + n], 0.f);
        g_tgt4[b][n] = make_float4(tgt[(b * 3 + 0) * NPTS + n],
                                   tgt[(b * 3 + 1) * NPTS + n],
                                   tgt[(b * 3 + 2) * NPTS + n], 0.f);
    }
}

// ---------------- seed selection (all iterations): bitonic sort ----------------
__global__ void seed_kernel(Keys K) {
    int it = blockIdx.x >> 3, b = blockIdx.x & 7;
    int tid = threadIdx.x; // 1024 threads
    unsigned ka = K.sa[it], kb = K.sb[it];
    __shared__ unsigned long long arr[NPTS];
    for (int n = tid; n < NPTS; n += 1024) {
        unsigned m = (unsigned)(b * NPTS + n);
        float key = g_logw[b][n] + gumbel_from_bits(rbits32(ka, kb, m));
        unsigned uk = float_mono(key);
        arr[n] = ((unsigned long long)(~uk) << 32) | (unsigned)n;
    }
    __syncthreads();
    for (int k = 2; k <= NPTS; k <<= 1) {
        for (int j = k >> 1; j > 0; j >>= 1) {
            for (int i = tid; i < NPTS; i += 1024) {
                int ixj = i ^ j;
                if (ixj > i) {
                    unsigned long long a = arr[i], c = arr[ixj];
                    bool up = ((i & k) == 0);
                    if ((a > c) == up) { arr[i] = c; arr[ixj] = a; }
                }
            }
            __syncthreads();
        }
    }
    for (int s0 = tid; s0 < NS; s0 += 1024) {
        int j = (int)(arr[s0] & 0xFFFFFFFFull);
        float4 sp = g_src4[b][j];
        sp.w = g_w[b][j];
        g_s4[it][b][s0] = sp;
        g_c4[it][b][s0] = g_tgt4[b][j];
    }
}

// ---------------- group selection: top-30 per row, warp per row ----------------
// Branchless per-lane top-6 cache + predicated pop + REDUX warp argmax.
// unroll 8 for deeper ILP across the ~250-cycle per-key dependency chains.
__global__ void __launch_bounds__(256) nn_kernel(Keys K) {
    int w = threadIdx.x >> 5, lane = threadIdx.x & 31;
    int r = blockIdx.x * 8 + w;
    int it = r >> 13;
    int rr = r & 8191;
    int b = rr >> 10, i = rr & 1023;
    unsigned ka = K.na[it], kb = K.nb[it];
    const float4* __restrict__ S = &g_s4[it][b][0];
    const float4* __restrict__ C = &g_c4[it][b][0];
    float4 si = S[i], ci = C[i];

    unsigned c0 = 0, c1 = 0, c2 = 0, c3 = 0, c4 = 0, c5 = 0;
    int j0 = 0, j1 = 0, j2 = 0, j3 = 0, j4 = 0, j5 = 0;

#define KEYFOR(jv, ukv) { \
    float4 sj = S[jv], cjv = C[jv]; \
    float dx = si.x - sj.x, dy = si.y - sj.y, dz = si.z - sj.z; \
    float ex = ci.x - cjv.x, ey = ci.y - cjv.y, ez = ci.z - cjv.z; \
    float d1 = sqrtf(__fmaf_rn(dx, dx, __fmaf_rn(dy, dy, __fmul_rn(dz, dz)))); \
    float d2 = sqrtf(__fmaf_rn(ex, ex, __fmaf_rn(ey, ey, __fmul_rn(ez, ez)))); \
    float dd = d1 - d2; \
    float lc = fmaxf(-__fmul_rn(__fmul_rn(dd, dd), 100.0f), -2.3025851f); \
    ukv = float_mono(lc + gumbel_from_bits(rbits32(ka, kb, (unsigned)rr * 1024u + (unsigned)(jv)))); \
}

#define BINSERT6(uk, jn) { \
    unsigned _u = (uk); int _j = (jn); \
    bool g0 = _u > c0, g1 = _u > c1, g2 = _u > c2; \
    bool g3 = _u > c3, g4 = _u > c4, g5 = _u > c5; \
    c5 = g5 ? (g4 ? c4 : _u) : c5;  j5 = g5 ? (g4 ? j4 : _j) : j5; \
    c4 = g4 ? (g3 ? c3 : _u) : c4;  j4 = g4 ? (g3 ? j3 : _j) : j4; \
    c3 = g3 ? (g2 ? c2 : _u) : c3;  j3 = g3 ? (g2 ? j2 : _j) : j3; \
    c2 = g2 ? (g1 ? c1 : _u) : c2;  j2 = g2 ? (g1 ? j1 : _j) : j2; \
    c1 = g1 ? (g0 ? c0 : _u) : c1;  j1 = g1 ? (g0 ? j0 : _j) : j1; \
    c0 = g0 ? _u : c0;              j0 = g0 ? _j : j0; \
}

#pragma unroll 8
    for (int t = 0; t < 32; t++) {
        int j = lane + t * 32;
        unsigned uk; KEYFOR(j, uk);
        BINSERT6(uk, j);
    }
    int nc = 6;
    unsigned mask = 0u;
    int* out = &g_nn[it][b][i][0];
    for (int sel = 0; sel < NG; sel++) {
        unsigned m = __reduce_max_sync(0xffffffffu, c0);
        unsigned jj = (c0 == m) ? (unsigned)j0 : 0xFFFFFFFFu;
        int bj = (int)__reduce_min_sync(0xffffffffu, jj);
        if (lane == 0) out[sel] = bj;
        bool pop = ((bj & 31) == lane);
        mask |= pop ? (1u << (bj >> 5)) : 0u;
        c0 = pop ? c1 : c0; j0 = pop ? j1 : j0;
        c1 = pop ? c2 : c1; j1 = pop ? j2 : j1;
        c2 = pop ? c3 : c2; j2 = pop ? j3 : j2;
        c3 = pop ? c4 : c3; j3 = pop ? j4 : j3;
        c4 = pop ? c5 : c4; j4 = pop ? j5 : j4;
        c5 = pop ? 0u : c5; j5 = pop ? 0  : j5;
        nc -= (int)pop;
        if (nc == 0) {   // cold: rebuild top-6 of this lane's unconsumed keys
            c0 = c1 = c2 = c3 = c4 = c5 = 0u;
            j0 = j1 = j2 = j3 = j4 = j5 = 0;
            for (int t = 0; t < 32; t++) {
                if ((mask >> t) & 1u) continue;
                int jn = lane + t * 32;
                unsigned uk; KEYFOR(jn, uk);
                BINSERT6(uk, jn);
            }
            int rem = 32 - __popc(mask);
            nc = rem < 6 ? rem : 6;
            if (nc == 0) nc = 1000;
        }
    }
#undef KEYFOR
#undef BINSERT6
}

// ---------------- weighted Kabsch via f32 one-sided Jacobi SVD ----------------
__global__ void kabsch_kernel() {
    int id = blockIdx.x * blockDim.x + threadIdx.x;
    if (id >= NIT * NB * NS) return;
    int it = id >> 13, rr = id & 8191;
    int b = rr >> 10, s = rr & 1023;
    const int* nn = &g_nn[it][b][s][0];
    const float4* __restrict__ S = &g_s4[it][b][0];
    const float4* __restrict__ C = &g_c4[it][b][0];
    float smx = 0, smy = 0, smz = 0, cmx = 0, cmy = 0, cmz = 0, wsum = 0;
    for (int g = 0; g < NG; g++) {
        int j = nn[g];
        float4 sp = S[j], cp = C[j];
        smx += sp.x; smy += sp.y; smz += sp.z;
        cmx += cp.x; cmy += cp.y; cmz += cp.z;
        wsum += sp.w;
    }
    const float inv30 = 1.0f / 30.0f;
    smx *= inv30; smy *= inv30; smz *= inv30;
    cmx *= inv30; cmy *= inv30; cmz *= inv30;
    float winv = 1.0f / wsum;
    float H[3][3] = {};
    for (int g = 0; g < NG; g++) {
        int j = nn[g];
        float4 sp = S[j], cp = C[j];
        float wn = sp.w * winv;
        float ax = sp.x - smx, ay = sp.y - smy, az = sp.z - smz;
        float bx = cp.x - cmx, by = cp.y - cmy, bz = cp.z - cmz;
        float wax = wn * ax, way = wn * ay, waz = wn * az;
        H[0][0] += wax * bx; H[0][1] += wax * by; H[0][2] += wax * bz;
        H[1][0] += way * bx; H[1][1] += way * by; H[1][2] += way * bz;
        H[2][0] += waz * bx; H[2][1] += waz * by; H[2][2] += waz * bz;
    }
    float W[3][3], V[3][3];
    for (int r = 0; r < 3; r++) for (int c = 0; c < 3; c++) { W[r][c] = H[r][c]; V[r][c] = (r == c) ? 1.f : 0.f; }
    const int PP[3] = {0, 0, 1}, QQ[3] = {1, 2, 2};
    for (int sweep = 0; sweep < 7; sweep++) {
        for (int pi = 0; pi < 3; pi++) {
            int p = PP[pi], q = QQ[pi];
            float app = W[0][p] * W[0][p] + W[1][p] * W[1][p] + W[2][p] * W[2][p];
            float aqq = W[0][q] * W[0][q] + W[1][q] * W[1][q] + W[2][q] * W[2][q];
            float apq = W[0][p] * W[0][q] + W[1][p] * W[1][q] + W[2][p] * W[2][q];
            if (fabsf(apq) < 1e-25f) continue;
            float zeta = (aqq - app) / (2.0f * apq);
            float t = copysignf(1.0f, zeta) / (fabsf(zeta) + sqrtf(1.0f + zeta * zeta));
            float cs = 1.0f / sqrtf(1.0f + t * t);
            float sn = cs * t;
            for (int r = 0; r < 3; r++) {
                float wp = W[r][p], wq = W[r][q];
                W[r][p] = cs * wp - sn * wq;
                W[r][q] = sn * wp + cs * wq;
                float vp = V[r][p], vq = V[r][q];
                V[r][p] = cs * vp - sn * vq;
                V[r][q] = sn * vp + cs * vq;
            }
        }
    }
    float n0 = W[0][0] * W[0][0] + W[1][0] * W[1][0] + W[2][0] * W[2][0];
    float n1 = W[0][1] * W[0][1] + W[1][1] * W[1][1] + W[2][1] * W[2][1];
    float n2 = W[0][2] * W[0][2] + W[1][2] * W[1][2] + W[2][2] * W[2][2];
    int i0 = 0, i1 = 1, i2 = 2;
    if (n1 > n0) { float tn = n0; n0 = n1; n1 = tn; int ti = i0; i0 = i1; i1 = ti; }
    if (n2 > n0) { float tn = n0; n0 = n2; n2 = tn; int ti = i0; i0 = i2; i2 = ti; }
    if (n2 > n1) { float tn = n1; n1 = n2; n2 = tn; int ti = i1; i1 = i2; i2 = ti; }
    float u1x = W[0][i0], u1y = W[1][i0], u1z = W[2][i0];
    float s1i = 1.0f / sqrtf(fmaxf(n0, 1e-30f));
    u1x *= s1i; u1y *= s1i; u1z *= s1i;
    float u2x = W[0][i1], u2y = W[1][i1], u2z = W[2][i1];
    float dp = u1x * u2x + u1y * u2y + u1z * u2z;
    u2x -= dp * u1x; u2y -= dp * u1y; u2z -= dp * u1z;
    float s2i = 1.0f / sqrtf(fmaxf(u2x * u2x + u2y * u2y + u2z * u2z, 1e-30f));
    u2x *= s2i; u2y *= s2i; u2z *= s2i;
    float u3x = u1y * u2z - u1z * u2y;
    float u3y = u1z * u2x - u1x * u2z;
    float u3z = u1x * u2y - u1y * u2x;
    float v1x = V[0][i0], v1y = V[1][i0], v1z = V[2][i0];
    float v2x = V[0][i1], v2y = V[1][i1], v2z = V[2][i1];
    float v3x = v1y * v2z - v1z * v2y;
    float v3y = v1z * v2x - v1x * v2z;
    float v3z = v1x * v2y - v1y * v2x;
    float R[3][3];
    R[0][0] = v1x * u1x + v2x * u2x + v3x * u3x;
    R[0][1] = v1x * u1y + v2x * u2y + v3x * u3y;
    R[0][2] = v1x * u1z + v2x * u2z + v3x * u3z;
    R[1][0] = v1y * u1x + v2y * u2x + v3y * u3x;
    R[1][1] = v1y * u1y + v2y * u2y + v3y * u3y;
    R[1][2] = v1y * u1z + v2y * u2z + v3y * u3z;
    R[2][0] = v1z * u1x + v2z * u2x + v3z * u3x;
    R[2][1] = v1z * u1y + v2z * u2y + v3z * u3y;
    R[2][2] = v1z * u1z + v2z * u2z + v3z * u3z;
    float tx = -(R[0][0] * smx + R[0][1] * smy + R[0][2] * smz) + cmx;
    float ty = -(R[1][0] * smx + R[1][1] * smy + R[1][2] * smz) + cmy;
    float tz = -(R[2][0] * smx + R[2][1] * smy + R[2][2] * smz) + cmz;
    float* o = &g_Rt[it][b][s][0];
    o[0] = R[0][0]; o[1] = R[0][1]; o[2] = R[0][2];
    o[3] = R[1][0]; o[4] = R[1][1]; o[5] = R[1][2];
    o[6] = R[2][0]; o[7] = R[2][1]; o[8] = R[2][2];
    o[9] = tx; o[10] = ty; o[11] = tz;
}

// ---------------- fitness + fused per-(it,b) argmax via atomicMax ----------
__global__ void __launch_bounds__(128) fitness_kernel() {
    int blk = blockIdx.x;              // 0..639
    int it = blk >> 6;
    int q = blk & 63;
    int b = q >> 3;
    int s = ((q & 7) << 7) + threadIdx.x;
    int tid = threadIdx.x;
    const float4* rt4 = (const float4*)&g_Rt[it][b][s][0];
    float4 A = rt4[0], B4 = rt4[1], C4 = rt4[2];
    ull q00 = pk2(A.x),  q01 = pk2(A.y),  q02 = pk2(A.z);
    ull q10 = pk2(A.w),  q11 = pk2(B4.x), q12 = pk2(B4.y);
    ull q20 = pk2(B4.z), q21 = pk2(B4.w), q22 = pk2(C4.x);
    ull qtx = pk2(C4.y), qty = pk2(C4.z), qtz = pk2(C4.w);
    __shared__ float ssx[256], ssy[256], ssz[256];
    __shared__ float ntx[256], nty[256], ntz[256];
    int cnt = 0;
    for (int cb = 0; cb < NPTS; cb += 256) {
        __syncthreads();
        for (int p = tid; p < 256; p += 128) {
            float4 P = g_src4[b][cb + p];
            ssx[p] = P.x; ssy[p] = P.y; ssz[p] = P.z;
            float4 T = g_tgt4[b][cb + p];
            ntx[p] = -T.x; nty[p] = -T.y; ntz[p] = -T.z;
        }
        __syncthreads();
#pragma unroll 4
        for (int p = 0; p < 128; p++) {
            ull Px = *(const ull*)&ssx[2 * p];
            ull Py = *(const ull*)&ssy[2 * p];
            ull Pz = *(const ull*)&ssz[2 * p];
            ull Tx = *(const ull*)&ntx[2 * p];
            ull Ty = *(const ull*)&nty[2 * p];
            ull Tz = *(const ull*)&ntz[2 * p];
            ull ex, ey, ez;
            FMA2(ex, q02, Pz, qtx); FMA2(ex, q01, Py, ex); FMA2(ex, q00, Px, ex); ADD2(ex, ex, Tx);
            FMA2(ey, q12, Pz, qty); FMA2(ey, q11, Py, ey); FMA2(ey, q10, Px, ey); ADD2(ey, ey, Ty);
            FMA2(ez, q22, Pz, qtz); FMA2(ez, q21, Py, ez); FMA2(ez, q20, Px, ez); ADD2(ez, ez, Tz);
            ull d2; MUL2(d2, ez, ez); FMA2(d2, ey, ey, d2); FMA2(d2, ex, ex, d2);
            float lo, hi; unpk(lo, hi, d2);
            cnt += (lo < 0.01f) ? 1 : 0;
            cnt += (hi < 0.01f) ? 1 : 0;
        }
    }
    // fused argmax: packed (count<<10)|(1023-s); block-reduce then one atomicMax
    unsigned packed = ((unsigned)cnt << 10) | (1023u - (unsigned)s);
    packed = __reduce_max_sync(0xffffffffu, packed);
    __shared__ unsigned wb[4];
    if ((tid & 31) == 0) wb[tid >> 5] = packed;
    __syncthreads();
    if (tid == 0) {
        unsigned m = max(max(wb[0], wb[1]), max(wb[2], wb[3]));
        atomicMax(&g_best[it][b], m);
    }
}

// ---------------- final selection across all iterations ----------------
__global__ void select_kernel(float* __restrict__ out) {
    int tid = threadIdx.x;
    __shared__ int bc_s[8], bs_s[8];
    __shared__ int flag;
    __shared__ float dist_s;
    if (tid == 0) dist_s = 1e8f;
    __syncthreads();
    for (int it = 0; it < NIT; it++) {
        if (tid < 8) {
            unsigned p = g_best[it][tid];
            bc_s[tid] = (int)(p >> 10);
            bs_s[tid] = 1023 - (int)(p & 1023u);
        }
        __syncthreads();
        if (tid == 0) {
            float s = 0.f;
            for (int i = 0; i < 8; i++) s += (float)bc_s[i] * (1.0f / 2048.0f);
            float vv = s * 0.125f;
            flag = (vv < dist_s) ? 1 : 0;
            if (flag) dist_s = vv;
        }
        __syncthreads();
        if (flag) {
            if (tid < 72) {
                int bb = tid / 9, e = tid % 9;
                out[tid] = g_Rt[it][bb][bs_s[bb]][e];
            } else if (tid < 96) {
                int qq = tid - 72, bb = qq / 3, e = qq % 3;
                out[tid] = g_Rt[it][bb][bs_s[bb]][9 + e];
            }
        }
        __syncthreads();
    }
}

// ---------------- launch ----------------
extern "C" void kernel_launch(void* const* d_in, const int* in_sizes, int n_in,
                              void* d_out, int out_size) {
    int wi = 2;
    if (n_in >= 3) {
        if (in_sizes[0] == NB * NPTS) wi = 0;
        else if (in_sizes[1] == NB * NPTS) wi = 1;
        else wi = 2;
    }
    int si = (wi == 0) ? 1 : 0;
    int ti = si + 1; if (ti == wi) ti++;
    const float* src = (const float*)d_in[si];
    const float* tgt = (const float*)d_in[ti];
    const float* wts = (const float*)d_in[wi];
    float* out = (float*)d_out;

    Keys K;
    for (int it = 0; it < NIT; it++) {
        unsigned f0, f1;
        tf2x32(0u, 42u, 0u, (unsigned)it, f0, f1);
        tf2x32(f0, f1, 0u, 0u, K.sa[it], K.sb[it]);
        tf2x32(f0, f1, 0u, 1u, K.na[it], K.nb[it]);
    }

    softmax_kernel<<<NB, 256>>>(wts, src, tgt);
    seed_kernel<<<NIT * NB, 1024>>>(K);
    nn_kernel<<<NIT * 1024, 256>>>(K);
    kabsch_kernel<<<640, 128>>>();
    fitness_kernel<<<NIT * 64, 128>>>();
    select_kernel<<<1, 128>>>(out);
}

// round 17
// speedup vs baseline: 2.6536x; 1.0954x over previous
#include <cuda_runtime.h>
#include <math.h>

#define NB    8
#define NPTS  2048
#define NS    1024
#define NG    30
#define NIT   10
#define HALF  5

typedef unsigned long long ull;

// ---------------- persistent device scratch (no allocations) ----------------
__device__ float  g_w[NB][NPTS];
__device__ float  g_logw[NB][NPTS];
__device__ float4 g_src4[NB][NPTS];
__device__ float4 g_tgt4[NB][NPTS];
__device__ float4 g_s4[NIT][NB][NS];
__device__ float4 g_c4[NIT][NB][NS];
__device__ int    g_nn[NIT][NB][NS][NG];
__device__ float  g_Rt[NIT][NB][NS][12];
__device__ unsigned g_best[NIT][NB];

struct Keys {
    unsigned sa[NIT], sb[NIT];
    unsigned na[NIT], nb[NIT];
};

// ---------------- threefry-2x32 (JAX), host+device ----------------
__host__ __device__ __forceinline__ void tf2x32(unsigned k0, unsigned k1,
                                                unsigned x0, unsigned x1,
                                                unsigned& o0, unsigned& o1) {
    unsigned ks2 = k0 ^ k1 ^ 0x1BD11BDAu;
    x0 += k0; x1 += k1;
#define TF_RND(r) { x0 += x1; x1 = (x1 << (r)) | (x1 >> (32 - (r))); x1 ^= x0; }
    TF_RND(13) TF_RND(15) TF_RND(26) TF_RND(6)
    x0 += k1;  x1 += ks2 + 1u;
    TF_RND(17) TF_RND(29) TF_RND(16) TF_RND(24)
    x0 += ks2; x1 += k0 + 2u;
    TF_RND(13) TF_RND(15) TF_RND(26) TF_RND(6)
    x0 += k0;  x1 += k1 + 3u;
    TF_RND(17) TF_RND(29) TF_RND(16) TF_RND(24)
    x0 += k1;  x1 += ks2 + 4u;
    TF_RND(13) TF_RND(15) TF_RND(26) TF_RND(6)
    x0 += ks2; x1 += k0 + 5u;
#undef TF_RND
    o0 = x0; o1 = x1;
}

__device__ __forceinline__ unsigned rbits32(unsigned ka, unsigned kb, unsigned m) {
    unsigned o0, o1;
    tf2x32(ka, kb, 0u, m, o0, o1);
    return o0 ^ o1;
}

__device__ __forceinline__ float gumbel_from_bits(unsigned bits) {
    float f = __uint_as_float((bits >> 9) | 0x3f800000u) - 1.0f;
    float u = fmaxf(1e-9f, f + 1e-9f);
    return -logf(-logf(u));
}

__device__ __forceinline__ unsigned float_mono(float x) {
    unsigned u = __float_as_uint(x);
    return (u & 0x80000000u) ? ~u : (u | 0x80000000u);
}

// ---------------- packed f32x2 helpers (per-element IEEE identical) ----------
#define FMA2(d,a,b,c) asm("fma.rn.f32x2 %0, %1, %2, %3;" : "=l"(d) : "l"(a), "l"(b), "l"(c))
#define ADD2(d,a,b)   asm("add.rn.f32x2 %0, %1, %2;" : "=l"(d) : "l"(a), "l"(b))
#define MUL2(d,a,b)   asm("mul.rn.f32x2 %0, %1, %2;" : "=l"(d) : "l"(a), "l"(b))

__device__ __forceinline__ ull pk2(float v) {
    ull r; asm("mov.b64 %0, {%1, %1};" : "=l"(r) : "f"(v)); return r;
}
__device__ __forceinline__ void unpk(float& lo, float& hi, ull d) {
    asm("mov.b64 {%0, %1}, %2;" : "=f"(lo), "=f"(hi) : "l"(d));
}

// ---------------- softmax + log + pack src/tgt + reset g_best ----------------
__global__ void softmax_kernel(const float* __restrict__ win,
                               const float* __restrict__ src,
                               const float* __restrict__ tgt) {
    int b = blockIdx.x, tid = threadIdx.x;
    if (tid < NIT) g_best[tid][b] = 0u;    // reset per replay (graph-safe)
    __shared__ float red[256];
    float mx = -3.402823466e38f;
    for (int n = tid; n < NPTS; n += 256) {
        float x = win[b * NPTS + n];
        if (isnan(x)) x = 1e-7f;
        if (isinf(x)) x = 1.0f;
        mx = fmaxf(mx, x);
    }
    red[tid] = mx; __syncthreads();
    for (int o = 128; o > 0; o >>= 1) { if (tid < o) red[tid] = fmaxf(red[tid], red[tid + o]); __syncthreads(); }
    mx = red[0]; __syncthreads();
    float s = 0.f;
    for (int n = tid; n < NPTS; n += 256) {
        float x = win[b * NPTS + n];
        if (isnan(x)) x = 1e-7f;
        if (isinf(x)) x = 1.0f;
        float e = expf(x - mx);
        g_w[b][n] = e;
        s += e;
    }
    red[tid] = s; __syncthreads();
    for (int o = 128; o > 0; o >>= 1) { if (tid < o) red[tid] += red[tid + o]; __syncthreads(); }
    s = red[0];
    for (int n = tid; n < NPTS; n += 256) {
        float wv = g_w[b][n] / s;
        g_w[b][n] = wv;
        g_logw[b][n] = logf(wv);
        g_src4[b][n] = make_float4(src[(b * 3 + 0) * NPTS + n],
                                   src[(b * 3 + 1) * NPTS + n],
                                   src[(b * 3 + 2) * NPTS + n], 0.f);
        g_tgt4[b][n] = make_float4(tgt[(b * 3 + 0) * NPTS + n],
                                   tgt[(b * 3 + 1) * NPTS + n],
                                   tgt[(b * 3 + 2) * NPTS + n], 0.f);
    }
}

// ---------------- seed selection (half the iterations): bitonic sort --------
__global__ void seed_kernel(Keys K, int itbase) {
    int it = itbase + (blockIdx.x >> 3), b = blockIdx.x & 7;
    int tid = threadIdx.x; // 1024 threads
    unsigned ka = K.sa[it], kb = K.sb[it];
    __shared__ unsigned long long arr[NPTS];
    for (int n = tid; n < NPTS; n += 1024) {
        unsigned m = (unsigned)(b * NPTS + n);
        float key = g_logw[b][n] + gumbel_from_bits(rbits32(ka, kb, m));
        unsigned uk = float_mono(key);
        arr[n] = ((unsigned long long)(~uk) << 32) | (unsigned)n;
    }
    __syncthreads();
    for (int k = 2; k <= NPTS; k <<= 1) {
        for (int j = k >> 1; j > 0; j >>= 1) {
            for (int i = tid; i < NPTS; i += 1024) {
                int ixj = i ^ j;
                if (ixj > i) {
                    unsigned long long a = arr[i], c = arr[ixj];
                    bool up = ((i & k) == 0);
                    if ((a > c) == up) { arr[i] = c; arr[ixj] = a; }
                }
            }
            __syncthreads();
        }
    }
    for (int s0 = tid; s0 < NS; s0 += 1024) {
        int j = (int)(arr[s0] & 0xFFFFFFFFull);
        float4 sp = g_src4[b][j];
        sp.w = g_w[b][j];
        g_s4[it][b][s0] = sp;
        g_c4[it][b][s0] = g_tgt4[b][j];
    }
}

// ---------------- group selection: top-30 per row, warp per row ----------------
__global__ void __launch_bounds__(256) nn_kernel(Keys K, int itbase) {
    int w = threadIdx.x >> 5, lane = threadIdx.x & 31;
    int r = blockIdx.x * 8 + w;              // 0..40959 (half)
    int it = itbase + (r >> 13);
    int rr = r & 8191;
    int b = rr >> 10, i = rr & 1023;
    unsigned ka = K.na[it], kb = K.nb[it];
    const float4* __restrict__ S = &g_s4[it][b][0];
    const float4* __restrict__ C = &g_c4[it][b][0];
    float4 si = S[i], ci = C[i];

    unsigned c0 = 0, c1 = 0, c2 = 0, c3 = 0, c4 = 0, c5 = 0;
    int j0 = 0, j1 = 0, j2 = 0, j3 = 0, j4 = 0, j5 = 0;

#define KEYFOR(jv, ukv) { \
    float4 sj = S[jv], cjv = C[jv]; \
    float dx = si.x - sj.x, dy = si.y - sj.y, dz = si.z - sj.z; \
    float ex = ci.x - cjv.x, ey = ci.y - cjv.y, ez = ci.z - cjv.z; \
    float d1 = sqrtf(__fmaf_rn(dx, dx, __fmaf_rn(dy, dy, __fmul_rn(dz, dz)))); \
    float d2 = sqrtf(__fmaf_rn(ex, ex, __fmaf_rn(ey, ey, __fmul_rn(ez, ez)))); \
    float dd = d1 - d2; \
    float lc = fmaxf(-__fmul_rn(__fmul_rn(dd, dd), 100.0f), -2.3025851f); \
    ukv = float_mono(lc + gumbel_from_bits(rbits32(ka, kb, (unsigned)rr * 1024u + (unsigned)(jv)))); \
}

#define BINSERT6(uk, jn) { \
    unsigned _u = (uk); int _j = (jn); \
    bool g0 = _u > c0, g1 = _u > c1, g2 = _u > c2; \
    bool g3 = _u > c3, g4 = _u > c4, g5 = _u > c5; \
    c5 = g5 ? (g4 ? c4 : _u) : c5;  j5 = g5 ? (g4 ? j4 : _j) : j5; \
    c4 = g4 ? (g3 ? c3 : _u) : c4;  j4 = g4 ? (g3 ? j3 : _j) : j4; \
    c3 = g3 ? (g2 ? c2 : _u) : c3;  j3 = g3 ? (g2 ? j2 : _j) : j3; \
    c2 = g2 ? (g1 ? c1 : _u) : c2;  j2 = g2 ? (g1 ? j1 : _j) : j2; \
    c1 = g1 ? (g0 ? c0 : _u) : c1;  j1 = g1 ? (g0 ? j0 : _j) : j1; \
    c0 = g0 ? _u : c0;              j0 = g0 ? _j : j0; \
}

#pragma unroll 8
    for (int t = 0; t < 32; t++) {
        int j = lane + t * 32;
        unsigned uk; KEYFOR(j, uk);
        BINSERT6(uk, j);
    }
    int nc = 6;
    unsigned mask = 0u;
    int* out = &g_nn[it][b][i][0];
    for (int sel = 0; sel < NG; sel++) {
        unsigned m = __reduce_max_sync(0xffffffffu, c0);
        unsigned jj = (c0 == m) ? (unsigned)j0 : 0xFFFFFFFFu;
        int bj = (int)__reduce_min_sync(0xffffffffu, jj);
        if (lane == 0) out[sel] = bj;
        bool pop = ((bj & 31) == lane);
        mask |= pop ? (1u << (bj >> 5)) : 0u;
        c0 = pop ? c1 : c0; j0 = pop ? j1 : j0;
        c1 = pop ? c2 : c1; j1 = pop ? j2 : j1;
        c2 = pop ? c3 : c2; j2 = pop ? j3 : j2;
        c3 = pop ? c4 : c3; j3 = pop ? j4 : j3;
        c4 = pop ? c5 : c4; j4 = pop ? j5 : j4;
        c5 = pop ? 0u : c5; j5 = pop ? 0  : j5;
        nc -= (int)pop;
        if (nc == 0) {   // cold: rebuild top-6 of this lane's unconsumed keys
            c0 = c1 = c2 = c3 = c4 = c5 = 0u;
            j0 = j1 = j2 = j3 = j4 = j5 = 0;
            for (int t = 0; t < 32; t++) {
                if ((mask >> t) & 1u) continue;
                int jn = lane + t * 32;
                unsigned uk; KEYFOR(jn, uk);
                BINSERT6(uk, jn);
            }
            int rem = 32 - __popc(mask);
            nc = rem < 6 ? rem : 6;
            if (nc == 0) nc = 1000;
        }
    }
#undef KEYFOR
#undef BINSERT6
}

// ---------------- weighted Kabsch via f32 one-sided Jacobi SVD ----------------
__global__ void kabsch_kernel(int itbase) {
    int id = blockIdx.x * blockDim.x + threadIdx.x;
    if (id >= HALF * NB * NS) return;
    int it = itbase + (id >> 13), rr = id & 8191;
    int b = rr >> 10, s = rr & 1023;
    const int* nn = &g_nn[it][b][s][0];
    const float4* __restrict__ S = &g_s4[it][b][0];
    const float4* __restrict__ C = &g_c4[it][b][0];
    float smx = 0, smy = 0, smz = 0, cmx = 0, cmy = 0, cmz = 0, wsum = 0;
    for (int g = 0; g < NG; g++) {
        int j = nn[g];
        float4 sp = S[j], cp = C[j];
        smx += sp.x; smy += sp.y; smz += sp.z;
        cmx += cp.x; cmy += cp.y; cmz += cp.z;
        wsum += sp.w;
    }
    const float inv30 = 1.0f / 30.0f;
    smx *= inv30; smy *= inv30; smz *= inv30;
    cmx *= inv30; cmy *= inv30; cmz *= inv30;
    float winv = 1.0f / wsum;
    float H[3][3] = {};
    for (int g = 0; g < NG; g++) {
        int j = nn[g];
        float4 sp = S[j], cp = C[j];
        float wn = sp.w * winv;
        float ax = sp.x - smx, ay = sp.y - smy, az = sp.z - smz;
        float bx = cp.x - cmx, by = cp.y - cmy, bz = cp.z - cmz;
        float wax = wn * ax, way = wn * ay, waz = wn * az;
        H[0][0] += wax * bx; H[0][1] += wax * by; H[0][2] += wax * bz;
        H[1][0] += way * bx; H[1][1] += way * by; H[1][2] += way * bz;
        H[2][0] += waz * bx; H[2][1] += waz * by; H[2][2] += waz * bz;
    }
    float W[3][3], V[3][3];
    for (int r = 0; r < 3; r++) for (int c = 0; c < 3; c++) { W[r][c] = H[r][c]; V[r][c] = (r == c) ? 1.f : 0.f; }
    const int PP[3] = {0, 0, 1}, QQ[3] = {1, 2, 2};
    for (int sweep = 0; sweep < 7; sweep++) {
        for (int pi = 0; pi < 3; pi++) {
            int p = PP[pi], q = QQ[pi];
            float app = W[0][p] * W[0][p] + W[1][p] * W[1][p] + W[2][p] * W[2][p];
            float aqq = W[0][q] * W[0][q] + W[1][q] * W[1][q] + W[2][q] * W[2][q];
            float apq = W[0][p] * W[0][q] + W[1][p] * W[1][q] + W[2][p] * W[2][q];
            if (fabsf(apq) < 1e-25f) continue;
            float zeta = (aqq - app) / (2.0f * apq);
            float t = copysignf(1.0f, zeta) / (fabsf(zeta) + sqrtf(1.0f + zeta * zeta));
            float cs = 1.0f / sqrtf(1.0f + t * t);
            float sn = cs * t;
            for (int r = 0; r < 3; r++) {
                float wp = W[r][p], wq = W[r][q];
                W[r][p] = cs * wp - sn * wq;
                W[r][q] = sn * wp + cs * wq;
                float vp = V[r][p], vq = V[r][q];
                V[r][p] = cs * vp - sn * vq;
                V[r][q] = sn * vp + cs * vq;
            }
        }
    }
    float n0 = W[0][0] * W[0][0] + W[1][0] * W[1][0] + W[2][0] * W[2][0];
    float n1 = W[0][1] * W[0][1] + W[1][1] * W[1][1] + W[2][1] * W[2][1];
    float n2 = W[0][2] * W[0][2] + W[1][2] * W[1][2] + W[2][2] * W[2][2];
    int i0 = 0, i1 = 1, i2 = 2;
    if (n1 > n0) { float tn = n0; n0 = n1; n1 = tn; int ti = i0; i0 = i1; i1 = ti; }
    if (n2 > n0) { float tn = n0; n0 = n2; n2 = tn; int ti = i0; i0 = i2; i2 = ti; }
    if (n2 > n1) { float tn = n1; n1 = n2; n2 = tn; int ti = i1; i1 = i2; i2 = ti; }
    float u1x = W[0][i0], u1y = W[1][i0], u1z = W[2][i0];
    float s1i = 1.0f / sqrtf(fmaxf(n0, 1e-30f));
    u1x *= s1i; u1y *= s1i; u1z *= s1i;
    float u2x = W[0][i1], u2y = W[1][i1], u2z = W[2][i1];
    float dp = u1x * u2x + u1y * u2y + u1z * u2z;
    u2x -= dp * u1x; u2y -= dp * u1y; u2z -= dp * u1z;
    float s2i = 1.0f / sqrtf(fmaxf(u2x * u2x + u2y * u2y + u2z * u2z, 1e-30f));
    u2x *= s2i; u2y *= s2i; u2z *= s2i;
    float u3x = u1y * u2z - u1z * u2y;
    float u3y = u1z * u2x - u1x * u2z;
    float u3z = u1x * u2y - u1y * u2x;
    float v1x = V[0][i0], v1y = V[1][i0], v1z = V[2][i0];
    float v2x = V[0][i1], v2y = V[1][i1], v2z = V[2][i1];
    float v3x = v1y * v2z - v1z * v2y;
    float v3y = v1z * v2x - v1x * v2z;
    float v3z = v1x * v2y - v1y * v2x;
    float R[3][3];
    R[0][0] = v1x * u1x + v2x * u2x + v3x * u3x;
    R[0][1] = v1x * u1y + v2x * u2y + v3x * u3y;
    R[0][2] = v1x * u1z + v2x * u2z + v3x * u3z;
    R[1][0] = v1y * u1x + v2y * u2x + v3y * u3x;
    R[1][1] = v1y * u1y + v2y * u2y + v3y * u3y;
    R[1][2] = v1y * u1z + v2y * u2z + v3y * u3z;
    R[2][0] = v1z * u1x + v2z * u2x + v3z * u3x;
    R[2][1] = v1z * u1y + v2z * u2y + v3z * u3y;
    R[2][2] = v1z * u1z + v2z * u2z + v3z * u3z;
    float tx = -(R[0][0] * smx + R[0][1] * smy + R[0][2] * smz) + cmx;
    float ty = -(R[1][0] * smx + R[1][1] * smy + R[1][2] * smz) + cmy;
    float tz = -(R[2][0] * smx + R[2][1] * smy + R[2][2] * smz) + cmz;
    float* o = &g_Rt[it][b][s][0];
    o[0] = R[0][0]; o[1] = R[0][1]; o[2] = R[0][2];
    o[3] = R[1][0]; o[4] = R[1][1]; o[5] = R[1][2];
    o[6] = R[2][0]; o[7] = R[2][1]; o[8] = R[2][2];
    o[9] = tx; o[10] = ty; o[11] = tz;
}

// ---------------- fitness + fused per-(it,b) argmax via atomicMax ----------
__global__ void __launch_bounds__(128) fitness_kernel(int itbase) {
    int blk = blockIdx.x;              // 0..319 (half)
    int it = itbase + (blk >> 6);
    int q = blk & 63;
    int b = q >> 3;
    int s = ((q & 7) << 7) + threadIdx.x;
    int tid = threadIdx.x;
    const float4* rt4 = (const float4*)&g_Rt[it][b][s][0];
    float4 A = rt4[0], B4 = rt4[1], C4 = rt4[2];
    ull q00 = pk2(A.x),  q01 = pk2(A.y),  q02 = pk2(A.z);
    ull q10 = pk2(A.w),  q11 = pk2(B4.x), q12 = pk2(B4.y);
    ull q20 = pk2(B4.z), q21 = pk2(B4.w), q22 = pk2(C4.x);
    ull qtx = pk2(C4.y), qty = pk2(C4.z), qtz = pk2(C4.w);
    __shared__ float ssx[256], ssy[256], ssz[256];
    __shared__ float ntx[256], nty[256], ntz[256];
    int cnt = 0;
    for (int cb = 0; cb < NPTS; cb += 256) {
        __syncthreads();
        for (int p = tid; p < 256; p += 128) {
            float4 P = g_src4[b][cb + p];
            ssx[p] = P.x; ssy[p] = P.y; ssz[p] = P.z;
            float4 T = g_tgt4[b][cb + p];
            ntx[p] = -T.x; nty[p] = -T.y; ntz[p] = -T.z;
        }
        __syncthreads();
#pragma unroll 4
        for (int p = 0; p < 128; p++) {
            ull Px = *(const ull*)&ssx[2 * p];
            ull Py = *(const ull*)&ssy[2 * p];
            ull Pz = *(const ull*)&ssz[2 * p];
            ull Tx = *(const ull*)&ntx[2 * p];
            ull Ty = *(const ull*)&nty[2 * p];
            ull Tz = *(const ull*)&ntz[2 * p];
            ull ex, ey, ez;
            FMA2(ex, q02, Pz, qtx); FMA2(ex, q01, Py, ex); FMA2(ex, q00, Px, ex); ADD2(ex, ex, Tx);
            FMA2(ey, q12, Pz, qty); FMA2(ey, q11, Py, ey); FMA2(ey, q10, Px, ey); ADD2(ey, ey, Ty);
            FMA2(ez, q22, Pz, qtz); FMA2(ez, q21, Py, ez); FMA2(ez, q20, Px, ez); ADD2(ez, ez, Tz);
            ull d2; MUL2(d2, ez, ez); FMA2(d2, ey, ey, d2); FMA2(d2, ex, ex, d2);
            float lo, hi; unpk(lo, hi, d2);
            cnt += (lo < 0.01f) ? 1 : 0;
            cnt += (hi < 0.01f) ? 1 : 0;
        }
    }
    unsigned packed = ((unsigned)cnt << 10) | (1023u - (unsigned)s);
    packed = __reduce_max_sync(0xffffffffu, packed);
    __shared__ unsigned wb[4];
    if ((tid & 31) == 0) wb[tid >> 5] = packed;
    __syncthreads();
    if (tid == 0) {
        unsigned m = max(max(wb[0], wb[1]), max(wb[2], wb[3]));
        atomicMax(&g_best[it][b], m);
    }
}

// ---------------- final selection across all iterations ----------------
__global__ void select_kernel(float* __restrict__ out) {
    int tid = threadIdx.x;
    __shared__ int bc_s[8], bs_s[8];
    __shared__ int flag;
    __shared__ float dist_s;
    if (tid == 0) dist_s = 1e8f;
    __syncthreads();
    for (int it = 0; it < NIT; it++) {
        if (tid < 8) {
            unsigned p = g_best[it][tid];
            bc_s[tid] = (int)(p >> 10);
            bs_s[tid] = 1023 - (int)(p & 1023u);
        }
        __syncthreads();
        if (tid == 0) {
            float s = 0.f;
            for (int i = 0; i < 8; i++) s += (float)bc_s[i] * (1.0f / 2048.0f);
            float vv = s * 0.125f;
            flag = (vv < dist_s) ? 1 : 0;
            if (flag) dist_s = vv;
        }
        __syncthreads();
        if (flag) {
            if (tid < 72) {
                int bb = tid / 9, e = tid % 9;
                out[tid] = g_Rt[it][bb][bs_s[bb]][e];
            } else if (tid < 96) {
                int qq = tid - 72, bb = qq / 3, e = qq % 3;
                out[tid] = g_Rt[it][bb][bs_s[bb]][9 + e];
            }
        }
        __syncthreads();
    }
}

// ---------------- two-stream fork/join plumbing (host-side, static init) ----
static cudaStream_t g_sA, g_sB;
static cudaEvent_t  g_e0, g_eA, g_eB;
static int g_stream_init = []() {
    cudaStreamCreateWithFlags(&g_sA, cudaStreamNonBlocking);
    cudaStreamCreateWithFlags(&g_sB, cudaStreamNonBlocking);
    cudaEventCreateWithFlags(&g_e0, cudaEventDisableTiming);
    cudaEventCreateWithFlags(&g_eA, cudaEventDisableTiming);
    cudaEventCreateWithFlags(&g_eB, cudaEventDisableTiming);
    return 0;
}();

// ---------------- launch ----------------
extern "C" void kernel_launch(void* const* d_in, const int* in_sizes, int n_in,
                              void* d_out, int out_size) {
    int wi = 2;
    if (n_in >= 3) {
        if (in_sizes[0] == NB * NPTS) wi = 0;
        else if (in_sizes[1] == NB * NPTS) wi = 1;
        else wi = 2;
    }
    int si = (wi == 0) ? 1 : 0;
    int ti = si + 1; if (ti == wi) ti++;
    const float* src = (const float*)d_in[si];
    const float* tgt = (const float*)d_in[ti];
    const float* wts = (const float*)d_in[wi];
    float* out = (float*)d_out;

    Keys K;
    for (int it = 0; it < NIT; it++) {
        unsigned f0, f1;
        tf2x32(0u, 42u, 0u, (unsigned)it, f0, f1);
        tf2x32(f0, f1, 0u, 0u, K.sa[it], K.sb[it]);
        tf2x32(f0, f1, 0u, 1u, K.na[it], K.nb[it]);
    }

    // main (capture) stream: softmax, then fork A/B halves, then join + select
    softmax_kernel<<<NB, 256>>>(wts, src, tgt);
    cudaEventRecord(g_e0, 0);
    cudaStreamWaitEvent(g_sA, g_e0, 0);
    cudaStreamWaitEvent(g_sB, g_e0, 0);

    seed_kernel<<<HALF * NB, 1024, 0, g_sA>>>(K, 0);
    seed_kernel<<<HALF * NB, 1024, 0, g_sB>>>(K, HALF);
    nn_kernel<<<HALF * 1024, 256, 0, g_sA>>>(K, 0);
    nn_kernel<<<HALF * 1024, 256, 0, g_sB>>>(K, HALF);
    kabsch_kernel<<<320, 128, 0, g_sA>>>(0);
    fitness_kernel<<<HALF * 64, 128, 0, g_sA>>>(0);
    kabsch_kernel<<<320, 128, 0, g_sB>>>(HALF);
    fitness_kernel<<<HALF * 64, 128, 0, g_sB>>>(HALF);

    cudaEventRecord(g_eA, g_sA);
    cudaEventRecord(g_eB, g_sB);
    cudaStreamWaitEvent(0, g_eA, 0);
    cudaStreamWaitEvent(0, g_eB, 0);
    select_kernel<<<1, 128>>>(out);
}